// round 12
// baseline (speedup 1.0000x reference)
#include <cuda_runtime.h>
#include <cuda_fp16.h>
#include <cstdint>

#define FULL 0xffffffffu

constexpr int NN   = 50000;
constexpr int FEA  = 213;
constexpr int H1   = 12, C1 = 16, D1 = 192;
constexpr int H2   = 8,  C2 = 8,  D2 = 64;
constexpr int PAIRS = 16384;
constexpr int EMAX = 800000;
constexpr int NHALF = 25088;

// ---------------- device scratch ----------------
__device__ __half g_h1[NN * D1];
__device__ __half g_x1h[NN * D1];
__device__ __half g_h2[NN * D2];
__device__ float  g_as1[NN * H1];
__device__ float  g_ad1[NN * H1];
__device__ float  g_as2[NN * H2];
__device__ float  g_ad2[NN * H2];
__device__ __align__(16) int g_deg[NN];
__device__ int    g_cursor[NN];
__device__ int    g_rowptr[NN + 1];
__device__ int    g_col[EMAX];

__device__ __forceinline__ float leaky(float x) { return x > 0.f ? x : 0.2f * x; }

// ---------------- CSR build (edges only; self-loops implicit) ---------------
__global__ void k_count(const int* __restrict__ ei, int E) {
    int i4 = (blockIdx.x * blockDim.x + threadIdx.x) * 4;
    if (i4 + 3 < E) {
        int4 d = *(const int4*)(ei + E + i4);
        atomicAdd(&g_deg[d.x], 1);
        atomicAdd(&g_deg[d.y], 1);
        atomicAdd(&g_deg[d.z], 1);
        atomicAdd(&g_deg[d.w], 1);
    } else {
        for (int i = i4; i < E; i++) atomicAdd(&g_deg[ei[E + i]], 1);
    }
}

__global__ void k_scan() {
    __shared__ int s[1024];
    int t = threadIdx.x;
    const int chunk = 52;
    int start = t * chunk;
    int end = start + chunk; if (end > NN) end = NN; if (start > NN) start = NN;
    int sum = 0;
    if (start < NN) {
        int full = (end - start) / 4;
        const int4* p = (const int4*)(g_deg + start);
        for (int i = 0; i < full; i++) { int4 v = p[i]; sum += v.x + v.y + v.z + v.w; }
        for (int i = start + full * 4; i < end; i++) sum += g_deg[i];
    }
    s[t] = sum;
    __syncthreads();
    for (int off = 1; off < 1024; off <<= 1) {
        int v = 0;
        if (t >= off) v = s[t - off];
        __syncthreads();
        s[t] += v;
        __syncthreads();
    }
    int run = s[t] - sum;
    for (int i = start; i < end; i++) { g_rowptr[i] = run; run += g_deg[i]; }
    if (t == 1023) g_rowptr[NN] = s[1023];
}

__global__ void k_scatter(const int* __restrict__ ei, int E) {
    int i4 = (blockIdx.x * blockDim.x + threadIdx.x) * 4;
    if (i4 + 3 < E) {
        int4 sv = *(const int4*)(ei + i4);
        int4 dv = *(const int4*)(ei + E + i4);
        int p0 = atomicAdd(&g_cursor[dv.x], 1); g_col[g_rowptr[dv.x] + p0] = sv.x;
        int p1 = atomicAdd(&g_cursor[dv.y], 1); g_col[g_rowptr[dv.y] + p1] = sv.y;
        int p2 = atomicAdd(&g_cursor[dv.z], 1); g_col[g_rowptr[dv.z] + p2] = sv.z;
        int p3 = atomicAdd(&g_cursor[dv.w], 1); g_col[g_rowptr[dv.w] + p3] = sv.w;
    } else {
        for (int i = i4; i < E; i++) {
            int src = ei[i], dst = ei[E + i];
            int pos = atomicAdd(&g_cursor[dst], 1);
            g_col[g_rowptr[dst] + pos] = src;
        }
    }
}

// ------------- fp16-split (Markidis) tensor-core GEMM, m16n8k16 -------------
__device__ __forceinline__ void split_pair(float x0, float x1,
                                           uint32_t& bg, uint32_t& sm) {
    __half2 b = __floats2half2_rn(x0, x1);
    float2 bf = __half22float2(b);
    __half2 s = __floats2half2_rn(x0 - bf.x, x1 - bf.y);
    bg = *reinterpret_cast<uint32_t*>(&b);
    sm = *reinterpret_cast<uint32_t*>(&s);
}
__device__ __forceinline__ void mma_f16(float* c, const uint32_t* a, const uint32_t* b) {
    asm volatile(
        "mma.sync.aligned.m16n8k16.row.col.f32.f16.f16.f32 "
        "{%0,%1,%2,%3}, {%4,%5,%6,%7}, {%8,%9}, {%0,%1,%2,%3};"
        : "+f"(c[0]), "+f"(c[1]), "+f"(c[2]), "+f"(c[3])
        : "r"(a[0]), "r"(a[1]), "r"(a[2]), "r"(a[3]), "r"(b[0]), "r"(b[1]));
}

// fp32 A, fp32 B, 3-term split (layer 1). C as __half. Fused attn epilogue.
template <int BM, int BN, int BK>
__global__ void __launch_bounds__(256)
k_gemm_hs(const float* __restrict__ A, const float* __restrict__ B,
          __half* __restrict__ Cm, int M, int K, int Nc,
          const float* __restrict__ aS, const float* __restrict__ aD,
          float* __restrict__ s_, float* __restrict__ d_) {
    constexpr int KP  = BK / 2;
    constexpr int AST = BM + 8;
    constexpr int BST = BN + 8;
    __shared__ uint32_t AsB[2][KP][AST], AsS[2][KP][AST];
    __shared__ uint32_t BsB[2][KP][BST], BsS[2][KP][BST];
    __shared__ float sAS[BN], sAD[BN];
    constexpr int ALD = BM * KP / 256;
    constexpr int BLD = BN * KP / 256;
    int t = threadIdx.x;
    int lane = t & 31, wid = t >> 5;
    int wm = wid & 3, wn = wid >> 2;
    int cq = lane & 3, gq = lane >> 2;
    int bm = blockIdx.y * BM, bn = blockIdx.x * BN;
    float acc[2][4][4] = {};
    uint32_t rabg[ALD], rasm[ALD], rbbg[BLD], rbsm[BLD];

    if (t < BN) { sAS[t] = aS[bn + t]; sAD[t] = aD[bn + t]; }

    #pragma unroll
    for (int u = 0; u < ALD; u++) {
        int i = t + 256 * u;
        int r = i >> 3, kp = i & 7;
        int row = bm + r;
        int k0 = 2 * kp;
        float x0 = (row < M && k0     < K) ? A[(long)row * K + k0]     : 0.f;
        float x1 = (row < M && k0 + 1 < K) ? A[(long)row * K + k0 + 1] : 0.f;
        uint32_t bg, sm;
        split_pair(x0, x1, bg, sm);
        AsB[0][kp][r] = bg; AsS[0][kp][r] = sm;
    }
    #pragma unroll
    for (int u = 0; u < BLD; u++) {
        int i = t + 256 * u;
        int col = i % BN, kp = i / BN;
        int k0 = 2 * kp;
        float x0 = (k0     < K) ? B[(long)k0       * Nc + bn + col] : 0.f;
        float x1 = (k0 + 1 < K) ? B[(long)(k0 + 1) * Nc + bn + col] : 0.f;
        uint32_t bg, sm;
        split_pair(x0, x1, bg, sm);
        BsB[0][kp][col] = bg; BsS[0][kp][col] = sm;
    }
    __syncthreads();

    int nTiles = (K + BK - 1) / BK;
    for (int tile = 0; tile < nTiles; tile++) {
        int buf = tile & 1;
        int k0n = (tile + 1) * BK;
        if (tile + 1 < nTiles) {
            #pragma unroll
            for (int u = 0; u < ALD; u++) {
                int i = t + 256 * u;
                int r = i >> 3, kp = i & 7;
                int row = bm + r;
                int k0 = k0n + 2 * kp;
                float x0 = (row < M && k0     < K) ? A[(long)row * K + k0]     : 0.f;
                float x1 = (row < M && k0 + 1 < K) ? A[(long)row * K + k0 + 1] : 0.f;
                split_pair(x0, x1, rabg[u], rasm[u]);
            }
            #pragma unroll
            for (int u = 0; u < BLD; u++) {
                int i = t + 256 * u;
                int col = i % BN, kp = i / BN;
                int k0 = k0n + 2 * kp;
                float x0 = (k0     < K) ? B[(long)k0       * Nc + bn + col] : 0.f;
                float x1 = (k0 + 1 < K) ? B[(long)(k0 + 1) * Nc + bn + col] : 0.f;
                split_pair(x0, x1, rbbg[u], rbsm[u]);
            }
        }
        {
            uint32_t ab[2][4], as_r[2][4];
            #pragma unroll
            for (int mt = 0; mt < 2; mt++) {
                int row = wm * 32 + mt * 16 + gq;
                ab[mt][0]   = AsB[buf][cq][row];     ab[mt][1]   = AsB[buf][cq][row + 8];
                ab[mt][2]   = AsB[buf][cq + 4][row]; ab[mt][3]   = AsB[buf][cq + 4][row + 8];
                as_r[mt][0] = AsS[buf][cq][row];     as_r[mt][1] = AsS[buf][cq][row + 8];
                as_r[mt][2] = AsS[buf][cq + 4][row]; as_r[mt][3] = AsS[buf][cq + 4][row + 8];
            }
            uint32_t bb[4][2], bs[4][2];
            #pragma unroll
            for (int nt = 0; nt < 4; nt++) {
                int col = wn * 32 + nt * 8 + gq;
                bb[nt][0] = BsB[buf][cq][col]; bb[nt][1] = BsB[buf][cq + 4][col];
                bs[nt][0] = BsS[buf][cq][col]; bs[nt][1] = BsS[buf][cq + 4][col];
            }
            #pragma unroll
            for (int mt = 0; mt < 2; mt++)
                #pragma unroll
                for (int nt = 0; nt < 4; nt++) {
                    mma_f16(acc[mt][nt], as_r[mt], bb[nt]);
                    mma_f16(acc[mt][nt], ab[mt],   bs[nt]);
                    mma_f16(acc[mt][nt], ab[mt],   bb[nt]);
                }
        }
        if (tile + 1 < nTiles) {
            __syncthreads();
            int nb = buf ^ 1;
            #pragma unroll
            for (int u = 0; u < ALD; u++) {
                int i = t + 256 * u;
                int r = i >> 3, kp = i & 7;
                AsB[nb][kp][r] = rabg[u]; AsS[nb][kp][r] = rasm[u];
            }
            #pragma unroll
            for (int u = 0; u < BLD; u++) {
                int i = t + 256 * u;
                int col = i % BN, kp = i / BN;
                BsB[nb][kp][col] = rbbg[u]; BsS[nb][kp][col] = rbsm[u];
            }
            __syncthreads();
        }
    }
    #pragma unroll
    for (int mt = 0; mt < 2; mt++) {
        int row0 = bm + wm * 32 + mt * 16 + gq;
        #pragma unroll
        for (int nt = 0; nt < 4; nt++) {
            int col = bn + wn * 32 + nt * 8 + 2 * cq;
            if (row0 < M)
                *(__half2*)&Cm[(long)row0 * Nc + col] =
                    __floats2half2_rn(acc[mt][nt][0], acc[mt][nt][1]);
            if (row0 + 8 < M)
                *(__half2*)&Cm[(long)(row0 + 8) * Nc + col] =
                    __floats2half2_rn(acc[mt][nt][2], acc[mt][nt][3]);
        }
        #pragma unroll
        for (int m = 0; m < 2; m++) {
            float sl = 0.f, dl = 0.f, sh = 0.f, dh = 0.f;
            #pragma unroll
            for (int p = 0; p < 2; p++) {
                int nt = 2 * m + p;
                int cl = wn * 32 + nt * 8 + 2 * cq;
                float a0 = sAS[cl], a1 = sAS[cl + 1];
                float b0 = sAD[cl], b1 = sAD[cl + 1];
                sl += acc[mt][nt][0] * a0 + acc[mt][nt][1] * a1;
                dl += acc[mt][nt][0] * b0 + acc[mt][nt][1] * b1;
                sh += acc[mt][nt][2] * a0 + acc[mt][nt][3] * a1;
                dh += acc[mt][nt][2] * b0 + acc[mt][nt][3] * b1;
            }
            sl += __shfl_xor_sync(FULL, sl, 1); sl += __shfl_xor_sync(FULL, sl, 2);
            dl += __shfl_xor_sync(FULL, dl, 1); dl += __shfl_xor_sync(FULL, dl, 2);
            sh += __shfl_xor_sync(FULL, sh, 1); sh += __shfl_xor_sync(FULL, sh, 2);
            dh += __shfl_xor_sync(FULL, dh, 1); dh += __shfl_xor_sync(FULL, dh, 2);
            if (cq == 0) {
                int hg = bn / C1 + 2 * wn + m;
                if (row0 < M)     { s_[(long)row0 * H1 + hg] = sl; d_[(long)row0 * H1 + hg] = dl; }
                if (row0 + 8 < M) { s_[(long)(row0 + 8) * H1 + hg] = sh; d_[(long)(row0 + 8) * H1 + hg] = dh; }
            }
        }
    }
}

// fp16 A (exact), fp32 B split -> 2-term MMA (layer 2). Fused attn epilogue.
template <int BM, int BN, int BK>
__global__ void __launch_bounds__(256)
k_gemm_h16(const __half* __restrict__ A, const float* __restrict__ B,
           __half* __restrict__ Cm, int M, int K, int Nc,
           const float* __restrict__ aS, const float* __restrict__ aD,
           float* __restrict__ s_, float* __restrict__ d_) {
    constexpr int KP  = BK / 2;
    constexpr int AST = BM + 8;
    constexpr int BST = BN + 8;
    __shared__ uint32_t AsB[2][KP][AST];
    __shared__ uint32_t BsB[2][KP][BST], BsS[2][KP][BST];
    __shared__ float sAS[BN], sAD[BN];
    constexpr int ALD = BM * KP / 256;
    constexpr int BLD = BN * KP / 256;
    int t = threadIdx.x;
    int lane = t & 31, wid = t >> 5;
    int wm = wid & 3, wn = wid >> 2;
    int cq = lane & 3, gq = lane >> 2;
    int bm = blockIdx.y * BM, bn = blockIdx.x * BN;
    float acc[2][4][4] = {};
    uint32_t rabg[ALD], rbbg[BLD], rbsm[BLD];

    if (t < BN) { sAS[t] = aS[bn + t]; sAD[t] = aD[bn + t]; }

    #pragma unroll
    for (int u = 0; u < ALD; u++) {
        int i = t + 256 * u;
        int r = i >> 3, kp = i & 7;
        int row = bm + r;
        int k0 = 2 * kp;
        uint32_t va = 0;
        if (row < M && k0 + 1 < K) va = *(const uint32_t*)&A[(long)row * K + k0];
        AsB[0][kp][r] = va;
    }
    #pragma unroll
    for (int u = 0; u < BLD; u++) {
        int i = t + 256 * u;
        int col = i % BN, kp = i / BN;
        int k0 = 2 * kp;
        float x0 = (k0     < K) ? B[(long)k0       * Nc + bn + col] : 0.f;
        float x1 = (k0 + 1 < K) ? B[(long)(k0 + 1) * Nc + bn + col] : 0.f;
        uint32_t bg, sm;
        split_pair(x0, x1, bg, sm);
        BsB[0][kp][col] = bg; BsS[0][kp][col] = sm;
    }
    __syncthreads();

    int nTiles = (K + BK - 1) / BK;
    for (int tile = 0; tile < nTiles; tile++) {
        int buf = tile & 1;
        int k0n = (tile + 1) * BK;
        if (tile + 1 < nTiles) {
            #pragma unroll
            for (int u = 0; u < ALD; u++) {
                int i = t + 256 * u;
                int r = i >> 3, kp = i & 7;
                int row = bm + r;
                int k0 = k0n + 2 * kp;
                uint32_t va = 0;
                if (row < M && k0 + 1 < K) va = *(const uint32_t*)&A[(long)row * K + k0];
                rabg[u] = va;
            }
            #pragma unroll
            for (int u = 0; u < BLD; u++) {
                int i = t + 256 * u;
                int col = i % BN, kp = i / BN;
                int k0 = k0n + 2 * kp;
                float x0 = (k0     < K) ? B[(long)k0       * Nc + bn + col] : 0.f;
                float x1 = (k0 + 1 < K) ? B[(long)(k0 + 1) * Nc + bn + col] : 0.f;
                split_pair(x0, x1, rbbg[u], rbsm[u]);
            }
        }
        {
            uint32_t ab[2][4];
            #pragma unroll
            for (int mt = 0; mt < 2; mt++) {
                int row = wm * 32 + mt * 16 + gq;
                ab[mt][0] = AsB[buf][cq][row];     ab[mt][1] = AsB[buf][cq][row + 8];
                ab[mt][2] = AsB[buf][cq + 4][row]; ab[mt][3] = AsB[buf][cq + 4][row + 8];
            }
            uint32_t bb[4][2], bs[4][2];
            #pragma unroll
            for (int nt = 0; nt < 4; nt++) {
                int col = wn * 32 + nt * 8 + gq;
                bb[nt][0] = BsB[buf][cq][col]; bb[nt][1] = BsB[buf][cq + 4][col];
                bs[nt][0] = BsS[buf][cq][col]; bs[nt][1] = BsS[buf][cq + 4][col];
            }
            #pragma unroll
            for (int mt = 0; mt < 2; mt++)
                #pragma unroll
                for (int nt = 0; nt < 4; nt++) {
                    mma_f16(acc[mt][nt], ab[mt], bs[nt]);
                    mma_f16(acc[mt][nt], ab[mt], bb[nt]);
                }
        }
        if (tile + 1 < nTiles) {
            __syncthreads();
            int nb = buf ^ 1;
            #pragma unroll
            for (int u = 0; u < ALD; u++) {
                int i = t + 256 * u;
                int r = i >> 3, kp = i & 7;
                AsB[nb][kp][r] = rabg[u];
            }
            #pragma unroll
            for (int u = 0; u < BLD; u++) {
                int i = t + 256 * u;
                int col = i % BN, kp = i / BN;
                BsB[nb][kp][col] = rbbg[u]; BsS[nb][kp][col] = rbsm[u];
            }
            __syncthreads();
        }
    }
    #pragma unroll
    for (int mt = 0; mt < 2; mt++) {
        int row0 = bm + wm * 32 + mt * 16 + gq;
        #pragma unroll
        for (int nt = 0; nt < 4; nt++) {
            int col = bn + wn * 32 + nt * 8 + 2 * cq;
            if (row0 < M)
                *(__half2*)&Cm[(long)row0 * Nc + col] =
                    __floats2half2_rn(acc[mt][nt][0], acc[mt][nt][1]);
            if (row0 + 8 < M)
                *(__half2*)&Cm[(long)(row0 + 8) * Nc + col] =
                    __floats2half2_rn(acc[mt][nt][2], acc[mt][nt][3]);
            int cl = wn * 32 + nt * 8 + 2 * cq;
            float a0 = sAS[cl], a1 = sAS[cl + 1];
            float b0 = sAD[cl], b1 = sAD[cl + 1];
            float sl = acc[mt][nt][0] * a0 + acc[mt][nt][1] * a1;
            float dl = acc[mt][nt][0] * b0 + acc[mt][nt][1] * b1;
            float sh = acc[mt][nt][2] * a0 + acc[mt][nt][3] * a1;
            float dh = acc[mt][nt][2] * b0 + acc[mt][nt][3] * b1;
            sl += __shfl_xor_sync(FULL, sl, 1); sl += __shfl_xor_sync(FULL, sl, 2);
            dl += __shfl_xor_sync(FULL, dl, 1); dl += __shfl_xor_sync(FULL, dl, 2);
            sh += __shfl_xor_sync(FULL, sh, 1); sh += __shfl_xor_sync(FULL, sh, 2);
            dh += __shfl_xor_sync(FULL, dh, 1); dh += __shfl_xor_sync(FULL, dh, 2);
            if (cq == 0) {
                int hg = bn / C2 + 4 * wn + nt;
                if (row0 < M)     { s_[(long)row0 * H2 + hg] = sl; d_[(long)row0 * H2 + hg] = dl; }
                if (row0 + 8 < M) { s_[(long)(row0 + 8) * H2 + hg] = sh; d_[(long)(row0 + 8) * H2 + hg] = dh; }
            }
        }
    }
}

// ---------------- layer-1 aggregation: software-pipelined gather ------------
__device__ __forceinline__ void acc8(float* acc, uint4 v, float w) {
    __half2* hv = reinterpret_cast<__half2*>(&v);
    #pragma unroll
    for (int q = 0; q < 4; q++) {
        float2 f = __half22float2(hv[q]);
        acc[2 * q]     += w * f.x;
        acc[2 * q + 1] += w * f.y;
    }
}

__global__ void k_agg1(const __half* __restrict__ h, const float* __restrict__ as_,
                       const float* __restrict__ ad_, const float* __restrict__ bias,
                       __half* __restrict__ out, int n0, int cnt) {
    constexpr int H = H1, D = D1;
    int warp = (blockIdx.x * blockDim.x + threadIdx.x) >> 5;
    int lane = threadIdx.x & 31;
    if (warp >= cnt) return;
    int node = n0 + warp;
    int r0 = g_rowptr[node];
    int r1 = g_rowptr[node + 1];

    float adv = (lane < H) ? ad_[node * H + lane] : 0.f;
    int myHead = (lane < 24) ? (lane >> 1) : 0;

    float acc[8] = {};
    float denom = 0.f;

    // implicit self-loop
    {
        float wS = (lane < H) ? __expf(leaky(__ldg(as_ + (long)node * H + lane) + adv)) : 0.f;
        denom += wS;
        float eS = __shfl_sync(FULL, wS, myHead);
        if (lane < 24) {
            uint4 v = *(const uint4*)(h + (long)node * D + lane * 8);
            acc8(acc, v, eS);
        }
    }

    // pipeline state for current 4-edge group
    int c0 = node, c1 = node, c2 = node, c3 = node;
    float a0 = 0.f, a1 = 0.f, a2 = 0.f, a3 = 0.f;
    uint4 v0 = {0,0,0,0}, v1 = {0,0,0,0}, v2 = {0,0,0,0}, v3 = {0,0,0,0};

    if (r0 < r1) {
        c0 = g_col[r0];
        c1 = (r0 + 1 < r1) ? g_col[r0 + 1] : node;
        c2 = (r0 + 2 < r1) ? g_col[r0 + 2] : node;
        c3 = (r0 + 3 < r1) ? g_col[r0 + 3] : node;
        if (lane < H) {
            a0 = __ldg(as_ + (long)c0 * H + lane);
            a1 = __ldg(as_ + (long)c1 * H + lane);
            a2 = __ldg(as_ + (long)c2 * H + lane);
            a3 = __ldg(as_ + (long)c3 * H + lane);
        }
        if (lane < 24) {
            v0 = *(const uint4*)(h + (long)c0 * D + lane * 8);
            v1 = *(const uint4*)(h + (long)c1 * D + lane * 8);
            v2 = *(const uint4*)(h + (long)c2 * D + lane * 8);
            v3 = *(const uint4*)(h + (long)c3 * D + lane * 8);
        }
    }

    for (int jj = r0; jj < r1; jj += 4) {
        int jn = jj + 4;
        // prefetch next group
        int d0 = node, d1 = node, d2 = node, d3 = node;
        float b0 = 0.f, b1 = 0.f, b2 = 0.f, b3 = 0.f;
        uint4 u0 = {0,0,0,0}, u1 = {0,0,0,0}, u2 = {0,0,0,0}, u3 = {0,0,0,0};
        if (jn < r1) {
            d0 = g_col[jn];
            d1 = (jn + 1 < r1) ? g_col[jn + 1] : node;
            d2 = (jn + 2 < r1) ? g_col[jn + 2] : node;
            d3 = (jn + 3 < r1) ? g_col[jn + 3] : node;
            if (lane < H) {
                b0 = __ldg(as_ + (long)d0 * H + lane);
                b1 = __ldg(as_ + (long)d1 * H + lane);
                b2 = __ldg(as_ + (long)d2 * H + lane);
                b3 = __ldg(as_ + (long)d3 * H + lane);
            }
            if (lane < 24) {
                u0 = *(const uint4*)(h + (long)d0 * D + lane * 8);
                u1 = *(const uint4*)(h + (long)d1 * D + lane * 8);
                u2 = *(const uint4*)(h + (long)d2 * D + lane * 8);
                u3 = *(const uint4*)(h + (long)d3 * D + lane * 8);
            }
        }
        // compute current group (tail padded with w=0)
        float w0 = (lane < H)                 ? __expf(leaky(a0 + adv)) : 0.f;
        float w1 = (lane < H && jj + 1 < r1) ? __expf(leaky(a1 + adv)) : 0.f;
        float w2 = (lane < H && jj + 2 < r1) ? __expf(leaky(a2 + adv)) : 0.f;
        float w3 = (lane < H && jj + 3 < r1) ? __expf(leaky(a3 + adv)) : 0.f;
        denom += (w0 + w1) + (w2 + w3);
        float e0 = __shfl_sync(FULL, w0, myHead);
        float e1 = __shfl_sync(FULL, w1, myHead);
        float e2 = __shfl_sync(FULL, w2, myHead);
        float e3 = __shfl_sync(FULL, w3, myHead);
        if (lane < 24) {
            acc8(acc, v0, e0);
            acc8(acc, v1, e1);
            acc8(acc, v2, e2);
            acc8(acc, v3, e3);
        }
        c0 = d0; c1 = d1; c2 = d2; c3 = d3;
        a0 = b0; a1 = b1; a2 = b2; a3 = b3;
        v0 = u0; v1 = u1; v2 = u2; v3 = u3;
    }

    float rden = __frcp_rn(denom);
    float rk = __shfl_sync(FULL, rden, myHead);
    if (lane < 24) {
        int off = lane * 8;
        const float4* bp = (const float4*)&bias[off];
        float4 b0 = bp[0], b1 = bp[1];
        float v[8];
        v[0] = acc[0] * rk + b0.x; v[1] = acc[1] * rk + b0.y;
        v[2] = acc[2] * rk + b0.z; v[3] = acc[3] * rk + b0.w;
        v[4] = acc[4] * rk + b1.x; v[5] = acc[5] * rk + b1.y;
        v[6] = acc[6] * rk + b1.z; v[7] = acc[7] * rk + b1.w;
        #pragma unroll
        for (int q = 0; q < 8; q++)
            v[q] = v[q] > 0.f ? v[q] : __expf(v[q]) - 1.f;
        uint4 pk;
        __half2* ph = reinterpret_cast<__half2*>(&pk);
        ph[0] = __floats2half2_rn(v[0], v[1]);
        ph[1] = __floats2half2_rn(v[2], v[3]);
        ph[2] = __floats2half2_rn(v[4], v[5]);
        ph[3] = __floats2half2_rn(v[6], v[7]);
        *(uint4*)(out + (long)node * D + off) = pk;
    }
}

// ---------------- layer-2 aggregation: software-pipelined gather ------------
__global__ void k_agg2(const __half* __restrict__ h, const float* __restrict__ as_,
                       const float* __restrict__ ad_, const float* __restrict__ bias,
                       float* __restrict__ out) {
    constexpr int H = H2, C = C2, D = D2;
    int warp = (blockIdx.x * blockDim.x + threadIdx.x) >> 5;
    int lane = threadIdx.x & 31;
    if (warp >= NN) return;
    int node = warp;
    int r0 = g_rowptr[node];
    int r1 = g_rowptr[node + 1];

    float adv = (lane < H) ? ad_[node * H + lane] : 0.f;
    int sl = lane >> 2;   // head for this lane's half2 (k2=2*lane, C=8)

    float2 acc = make_float2(0.f, 0.f);
    float denom = 0.f;

    // implicit self-loop
    {
        float wS = (lane < H) ? __expf(leaky(__ldg(as_ + (long)node * H + lane) + adv)) : 0.f;
        denom += wS;
        float e = __shfl_sync(FULL, wS, sl);
        float2 v = __half22float2(((const __half2*)(h + (long)node * D))[lane]);
        acc.x += e * v.x;
        acc.y += e * v.y;
    }

    int c0 = node, c1 = node, c2 = node, c3 = node;
    float a0 = 0.f, a1 = 0.f, a2 = 0.f, a3 = 0.f;
    __half2 v0 = __half2half2(__float2half(0.f)), v1 = v0, v2 = v0, v3 = v0;

    if (r0 < r1) {
        c0 = g_col[r0];
        c1 = (r0 + 1 < r1) ? g_col[r0 + 1] : node;
        c2 = (r0 + 2 < r1) ? g_col[r0 + 2] : node;
        c3 = (r0 + 3 < r1) ? g_col[r0 + 3] : node;
        if (lane < H) {
            a0 = __ldg(as_ + (long)c0 * H + lane);
            a1 = __ldg(as_ + (long)c1 * H + lane);
            a2 = __ldg(as_ + (long)c2 * H + lane);
            a3 = __ldg(as_ + (long)c3 * H + lane);
        }
        v0 = ((const __half2*)(h + (long)c0 * D))[lane];
        v1 = ((const __half2*)(h + (long)c1 * D))[lane];
        v2 = ((const __half2*)(h + (long)c2 * D))[lane];
        v3 = ((const __half2*)(h + (long)c3 * D))[lane];
    }

    for (int jj = r0; jj < r1; jj += 4) {
        int jn = jj + 4;
        int d0 = node, d1 = node, d2 = node, d3 = node;
        float b0 = 0.f, b1 = 0.f, b2 = 0.f, b3 = 0.f;
        __half2 u0 = v0, u1 = v0, u2 = v0, u3 = v0;
        if (jn < r1) {
            d0 = g_col[jn];
            d1 = (jn + 1 < r1) ? g_col[jn + 1] : node;
            d2 = (jn + 2 < r1) ? g_col[jn + 2] : node;
            d3 = (jn + 3 < r1) ? g_col[jn + 3] : node;
            if (lane < H) {
                b0 = __ldg(as_ + (long)d0 * H + lane);
                b1 = __ldg(as_ + (long)d1 * H + lane);
                b2 = __ldg(as_ + (long)d2 * H + lane);
                b3 = __ldg(as_ + (long)d3 * H + lane);
            }
            u0 = ((const __half2*)(h + (long)d0 * D))[lane];
            u1 = ((const __half2*)(h + (long)d1 * D))[lane];
            u2 = ((const __half2*)(h + (long)d2 * D))[lane];
            u3 = ((const __half2*)(h + (long)d3 * D))[lane];
        }
        float w0 = (lane < H)                 ? __expf(leaky(a0 + adv)) : 0.f;
        float w1 = (lane < H && jj + 1 < r1) ? __expf(leaky(a1 + adv)) : 0.f;
        float w2 = (lane < H && jj + 2 < r1) ? __expf(leaky(a2 + adv)) : 0.f;
        float w3 = (lane < H && jj + 3 < r1) ? __expf(leaky(a3 + adv)) : 0.f;
        denom += (w0 + w1) + (w2 + w3);
        float e0 = __shfl_sync(FULL, w0, sl);
        float e1 = __shfl_sync(FULL, w1, sl);
        float e2 = __shfl_sync(FULL, w2, sl);
        float e3 = __shfl_sync(FULL, w3, sl);
        float2 f0 = __half22float2(v0), f1 = __half22float2(v1);
        float2 f2 = __half22float2(v2), f3 = __half22float2(v3);
        acc.x += e0 * f0.x + e1 * f1.x + e2 * f2.x + e3 * f3.x;
        acc.y += e0 * f0.y + e1 * f1.y + e2 * f2.y + e3 * f3.y;
        c0 = d0; c1 = d1; c2 = d2; c3 = d3;
        a0 = b0; a1 = b1; a2 = b2; a3 = b3;
        v0 = u0; v1 = u1; v2 = u2; v3 = u3;
    }

    float rden = __frcp_rn(denom);
    float rk = __shfl_sync(FULL, rden, sl);
    int k2 = 2 * lane;
    float2 bv = *(const float2*)&bias[k2];
    float vx = acc.x * rk + bv.x;
    float vy = acc.y * rk + bv.y;
    vx = vx > 0.f ? vx : __expf(vx) - 1.f;
    vy = vy > 0.f ? vy : __expf(vy) - 1.f;
    *(float2*)&out[(long)node * D + k2] = make_float2(vx, vy);
}

// ---------------- pair scoring head ----------------
__global__ void k_pair(const float* __restrict__ x, const int* __restrict__ n1,
                       const int* __restrict__ n2, const float* __restrict__ linW,
                       const float* __restrict__ linb, float* __restrict__ y) {
    int warp = (blockIdx.x * blockDim.x + threadIdx.x) >> 5;
    int lane = threadIdx.x & 31;
    if (warp >= PAIRS) return;
    int a = n1[warp], b = n2[warp];
    float p0 = 0.f, p1 = 0.f;
    #pragma unroll
    for (int i = 0; i < 4; i++) {
        int k = lane + 32 * i;
        float xv = (k < D2) ? x[(long)a * D2 + k] : x[(long)b * D2 + (k - D2)];
        p0 += xv * linW[k * 2 + 0];
        p1 += xv * linW[k * 2 + 1];
    }
    #pragma unroll
    for (int off = 16; off; off >>= 1) {
        p0 += __shfl_xor_sync(FULL, p0, off);
        p1 += __shfl_xor_sync(FULL, p1, off);
    }
    if (lane == 0) {
        float z0 = p0 + linb[0], z1 = p1 + linb[1];
        y[warp * 2 + 0] = 1.f / (1.f + __expf(-z0));
        y[warp * 2 + 1] = 1.f / (1.f + __expf(-z1));
    }
}

// ---------------- launcher ----------------
extern "C" void kernel_launch(void* const* d_in, const int* in_sizes, int n_in,
                              void* d_out, int out_size) {
    const float* features = (const float*)d_in[0];
    const int*   edge_index = (const int*)d_in[1];
    const int*   n1 = (const int*)d_in[2];
    const int*   n2 = (const int*)d_in[3];
    const float* W1 = (const float*)d_in[4];
    const float* attS1 = (const float*)d_in[5];
    const float* attD1 = (const float*)d_in[6];
    const float* b1 = (const float*)d_in[7];
    const float* W2 = (const float*)d_in[8];
    const float* attS2 = (const float*)d_in[9];
    const float* attD2 = (const float*)d_in[10];
    const float* b2 = (const float*)d_in[11];
    const float* linW = (const float*)d_in[12];
    const float* linb = (const float*)d_in[13];

    float* out  = (float*)d_out;
    float* y    = out;
    float* xout = out + PAIRS * 2;

    int E = in_sizes[1] / 2;

    __half *p_h1, *p_x1h, *p_h2;
    float *p_as1, *p_ad1, *p_as2, *p_ad2;
    int *p_deg, *p_cursor;
    cudaGetSymbolAddress((void**)&p_h1, g_h1);
    cudaGetSymbolAddress((void**)&p_x1h, g_x1h);
    cudaGetSymbolAddress((void**)&p_h2, g_h2);
    cudaGetSymbolAddress((void**)&p_as1, g_as1);
    cudaGetSymbolAddress((void**)&p_ad1, g_ad1);
    cudaGetSymbolAddress((void**)&p_as2, g_as2);
    cudaGetSymbolAddress((void**)&p_ad2, g_ad2);
    cudaGetSymbolAddress((void**)&p_deg, g_deg);
    cudaGetSymbolAddress((void**)&p_cursor, g_cursor);

    static cudaStream_t s2 = nullptr;
    static cudaEvent_t evFork = nullptr, evJoin = nullptr, evA = nullptr, evG = nullptr;
    if (!s2) {
        cudaStreamCreateWithFlags(&s2, cudaStreamNonBlocking);
        cudaEventCreateWithFlags(&evFork, cudaEventDisableTiming);
        cudaEventCreateWithFlags(&evJoin, cudaEventDisableTiming);
        cudaEventCreateWithFlags(&evA, cudaEventDisableTiming);
        cudaEventCreateWithFlags(&evG, cudaEventDisableTiming);
    }

    int e4blocks = ((E + 3) / 4 + 255) / 256;

    // fork: CSR build on s2 overlaps GEMM1 (with fused attn) on main stream
    cudaEventRecord(evFork, 0);
    cudaStreamWaitEvent(s2, evFork, 0);

    cudaMemsetAsync(p_deg, 0, NN * sizeof(int), s2);
    cudaMemsetAsync(p_cursor, 0, NN * sizeof(int), s2);
    k_count<<<e4blocks, 256, 0, s2>>>(edge_index, E);
    k_scan<<<1, 1024, 0, s2>>>();
    k_scatter<<<e4blocks, 256, 0, s2>>>(edge_index, E);
    cudaEventRecord(evJoin, s2);

    {
        dim3 grid(D1 / 64, (NN + 127) / 128);
        k_gemm_hs<128, 64, 16><<<grid, 256>>>(features, W1, p_h1, NN, FEA, D1,
                                              attS1, attD1, p_as1, p_ad1);
    }

    cudaStreamWaitEvent(0, evJoin, 0);

    // agg1 lo half, then pipeline: GEMM2-lo on s2 overlaps agg1 hi half
    k_agg1<<<(NHALF * 32 + 255) / 256, 256>>>(p_h1, p_as1, p_ad1, b1, p_x1h, 0, NHALF);
    cudaEventRecord(evA, 0);
    cudaStreamWaitEvent(s2, evA, 0);
    {
        dim3 grid(D2 / 64, NHALF / 128);
        k_gemm_h16<128, 64, 16><<<grid, 256, 0, s2>>>(p_x1h, W2, p_h2, NHALF, D1, D2,
                                                      attS2, attD2, p_as2, p_ad2);
    }
    cudaEventRecord(evG, s2);

    k_agg1<<<((NN - NHALF) * 32 + 255) / 256, 256>>>(p_h1, p_as1, p_ad1, b1, p_x1h, NHALF, NN - NHALF);
    {
        dim3 grid(D2 / 64, (NN - NHALF + 127) / 128);
        k_gemm_h16<128, 64, 16><<<grid, 256>>>(p_x1h + (long)NHALF * D1, W2,
                                               p_h2 + (long)NHALF * D2, NN - NHALF, D1, D2,
                                               attS2, attD2,
                                               p_as2 + (long)NHALF * H2, p_ad2 + (long)NHALF * H2);
    }
    cudaStreamWaitEvent(0, evG, 0);

    k_agg2<<<(NN * 32 + 255) / 256, 256>>>(p_h2, p_as2, p_ad2, b2, xout);

    // Pair head
    k_pair<<<(PAIRS * 32 + 255) / 256, 256>>>(xout, n1, n2, linW, linb, y);
}

// round 13
// speedup vs baseline: 1.3544x; 1.3544x over previous
#include <cuda_runtime.h>
#include <cuda_fp16.h>
#include <cstdint>

#define FULL 0xffffffffu

constexpr int NN   = 50000;
constexpr int FEA  = 213;
constexpr int H1   = 12, C1 = 16, D1 = 192;
constexpr int H2   = 8,  C2 = 8,  D2 = 64;
constexpr int PAIRS = 16384;
constexpr int EMAX = 800000;
constexpr int NHALF = 25088;
constexpr int AKP1 = 112;   // padded k-pair count for K=213 (14 tiles x 8)
constexpr int KP2  = 96;    // k-pairs for K=192

// ---------------- device scratch ----------------
__device__ __half g_h1[NN * D1];
__device__ __half g_x1h[NN * D1];
__device__ __half g_h2[NN * D2];
__device__ float  g_as1[NN * H1];
__device__ float  g_ad1[NN * H1];
__device__ float  g_as2[NN * H2];
__device__ float  g_ad2[NN * H2];
__device__ uint32_t g_fAb[NN * AKP1];   // features big plane (half2 k-pairs)
__device__ uint32_t g_fAs[NN * AKP1];   // features small plane
__device__ uint32_t g_w1b[AKP1 * D1], g_w1s[AKP1 * D1];
__device__ uint32_t g_w2b[KP2 * D2],  g_w2s[KP2 * D2];
__device__ __align__(16) int g_deg[NN];
__device__ int    g_cursor[NN];
__device__ int    g_rowptr[NN + 1];
__device__ int    g_col[EMAX];

__device__ __forceinline__ float leaky(float x) { return x > 0.f ? x : 0.2f * x; }

// ---------------- CSR build (edges only; self-loops implicit) ---------------
__global__ void k_count(const int* __restrict__ ei, int E) {
    int i4 = (blockIdx.x * blockDim.x + threadIdx.x) * 4;
    if (i4 + 3 < E) {
        int4 d = *(const int4*)(ei + E + i4);
        atomicAdd(&g_deg[d.x], 1);
        atomicAdd(&g_deg[d.y], 1);
        atomicAdd(&g_deg[d.z], 1);
        atomicAdd(&g_deg[d.w], 1);
    } else {
        for (int i = i4; i < E; i++) atomicAdd(&g_deg[ei[E + i]], 1);
    }
}

__global__ void k_scan() {
    __shared__ int s[1024];
    int t = threadIdx.x;
    const int chunk = 52;
    int start = t * chunk;
    int end = start + chunk; if (end > NN) end = NN; if (start > NN) start = NN;
    int sum = 0;
    if (start < NN) {
        int full = (end - start) / 4;
        const int4* p = (const int4*)(g_deg + start);
        for (int i = 0; i < full; i++) { int4 v = p[i]; sum += v.x + v.y + v.z + v.w; }
        for (int i = start + full * 4; i < end; i++) sum += g_deg[i];
    }
    s[t] = sum;
    __syncthreads();
    for (int off = 1; off < 1024; off <<= 1) {
        int v = 0;
        if (t >= off) v = s[t - off];
        __syncthreads();
        s[t] += v;
        __syncthreads();
    }
    int run = s[t] - sum;
    for (int i = start; i < end; i++) { g_rowptr[i] = run; run += g_deg[i]; }
    if (t == 1023) g_rowptr[NN] = s[1023];
}

__global__ void k_scatter(const int* __restrict__ ei, int E) {
    int i4 = (blockIdx.x * blockDim.x + threadIdx.x) * 4;
    if (i4 + 3 < E) {
        int4 sv = *(const int4*)(ei + i4);
        int4 dv = *(const int4*)(ei + E + i4);
        int p0 = atomicAdd(&g_cursor[dv.x], 1); g_col[g_rowptr[dv.x] + p0] = sv.x;
        int p1 = atomicAdd(&g_cursor[dv.y], 1); g_col[g_rowptr[dv.y] + p1] = sv.y;
        int p2 = atomicAdd(&g_cursor[dv.z], 1); g_col[g_rowptr[dv.z] + p2] = sv.z;
        int p3 = atomicAdd(&g_cursor[dv.w], 1); g_col[g_rowptr[dv.w] + p3] = sv.w;
    } else {
        for (int i = i4; i < E; i++) {
            int src = ei[i], dst = ei[E + i];
            int pos = atomicAdd(&g_cursor[dst], 1);
            g_col[g_rowptr[dst] + pos] = src;
        }
    }
}

// ---------------- operand pre-split (Markidis big/small, done once) ----------
__device__ __forceinline__ void split_pair(float x0, float x1,
                                           uint32_t& bg, uint32_t& sm) {
    __half2 b = __floats2half2_rn(x0, x1);
    float2 bf = __half22float2(b);
    __half2 s = __floats2half2_rn(x0 - bf.x, x1 - bf.y);
    bg = *reinterpret_cast<uint32_t*>(&b);
    sm = *reinterpret_cast<uint32_t*>(&s);
}

__global__ void k_split_feat(const float* __restrict__ f) {
    long idx = (long)blockIdx.x * blockDim.x + threadIdx.x;
    if (idx >= (long)NN * AKP1) return;
    int row = idx / AKP1, kp = idx % AKP1;
    int k0 = 2 * kp;
    float x0 = (k0     < FEA) ? f[(long)row * FEA + k0]     : 0.f;
    float x1 = (k0 + 1 < FEA) ? f[(long)row * FEA + k0 + 1] : 0.f;
    split_pair(x0, x1, g_fAb[idx], g_fAs[idx]);
}

__global__ void k_split_w1(const float* __restrict__ w) {
    int idx = blockIdx.x * blockDim.x + threadIdx.x;
    if (idx >= AKP1 * D1) return;
    int kp = idx / D1, col = idx % D1;
    int k0 = 2 * kp;
    float x0 = (k0     < FEA) ? w[(long)k0       * D1 + col] : 0.f;
    float x1 = (k0 + 1 < FEA) ? w[(long)(k0 + 1) * D1 + col] : 0.f;
    split_pair(x0, x1, g_w1b[idx], g_w1s[idx]);
}

__global__ void k_split_w2(const float* __restrict__ w) {
    int idx = blockIdx.x * blockDim.x + threadIdx.x;
    if (idx >= KP2 * D2) return;
    int kp = idx / D2, col = idx % D2;
    int k0 = 2 * kp;
    float x0 = w[(long)k0       * D2 + col];
    float x1 = w[(long)(k0 + 1) * D2 + col];
    split_pair(x0, x1, g_w2b[idx], g_w2s[idx]);
}

// ------------- fp16-split tensor-core GEMM, m16n8k16, pre-split loads -------
__device__ __forceinline__ void mma_f16(float* c, const uint32_t* a, const uint32_t* b) {
    asm volatile(
        "mma.sync.aligned.m16n8k16.row.col.f32.f16.f16.f32 "
        "{%0,%1,%2,%3}, {%4,%5,%6,%7}, {%8,%9}, {%0,%1,%2,%3};"
        : "+f"(c[0]), "+f"(c[1]), "+f"(c[2]), "+f"(c[3])
        : "r"(a[0]), "r"(a[1]), "r"(a[2]), "r"(a[3]), "r"(b[0]), "r"(b[1]));
}

// Layer 1: A planes [M][AKP], B planes [AKP][Nc]; 3-term split MMA.
// Fused attention epilogue (C1=16: 2 heads/warp). Pure LDG loads, no cvt.
template <int BM, int BN>
__global__ void __launch_bounds__(256)
k_gemm_hs(const uint32_t* __restrict__ Ab, const uint32_t* __restrict__ As_,
          const uint32_t* __restrict__ Bb, const uint32_t* __restrict__ Bs_,
          __half* __restrict__ Cm, int M, int AKP, int Nc,
          const float* __restrict__ aS, const float* __restrict__ aD,
          float* __restrict__ s_, float* __restrict__ d_) {
    constexpr int KP  = 8;
    constexpr int AST = BM + 8;
    constexpr int BST = BN + 8;
    __shared__ uint32_t AsB[2][KP][AST], AsS[2][KP][AST];
    __shared__ uint32_t BsB[2][KP][BST], BsS[2][KP][BST];
    __shared__ float sAS[BN], sAD[BN];
    constexpr int ALD = BM * KP / 256;   // 4
    constexpr int BLD = BN * KP / 256;   // 2
    int t = threadIdx.x;
    int lane = t & 31, wid = t >> 5;
    int wm = wid & 3, wn = wid >> 2;
    int cq = lane & 3, gq = lane >> 2;
    int bm = blockIdx.y * BM, bn = blockIdx.x * BN;
    float acc[2][4][4] = {};
    uint32_t rabg[ALD], rasm[ALD], rbbg[BLD], rbsm[BLD];

    if (t < BN) { sAS[t] = aS[bn + t]; sAD[t] = aD[bn + t]; }

    #pragma unroll
    for (int u = 0; u < ALD; u++) {
        int i = t + 256 * u;
        int r = i >> 3, kp = i & 7;
        int row = bm + r;
        long o = (long)row * AKP + kp;
        AsB[0][kp][r] = (row < M) ? Ab[o] : 0u;
        AsS[0][kp][r] = (row < M) ? As_[o] : 0u;
    }
    #pragma unroll
    for (int u = 0; u < BLD; u++) {
        int i = t + 256 * u;
        int col = i % BN, kp = i / BN;
        long o = (long)kp * Nc + bn + col;
        BsB[0][kp][col] = Bb[o];
        BsS[0][kp][col] = Bs_[o];
    }
    __syncthreads();

    int nTiles = AKP / KP;
    for (int tile = 0; tile < nTiles; tile++) {
        int buf = tile & 1;
        int kbase = (tile + 1) * KP;
        if (tile + 1 < nTiles) {
            #pragma unroll
            for (int u = 0; u < ALD; u++) {
                int i = t + 256 * u;
                int r = i >> 3, kp = i & 7;
                int row = bm + r;
                long o = (long)row * AKP + kbase + kp;
                rabg[u] = (row < M) ? Ab[o] : 0u;
                rasm[u] = (row < M) ? As_[o] : 0u;
            }
            #pragma unroll
            for (int u = 0; u < BLD; u++) {
                int i = t + 256 * u;
                int col = i % BN, kp = i / BN;
                long o = (long)(kbase + kp) * Nc + bn + col;
                rbbg[u] = Bb[o];
                rbsm[u] = Bs_[o];
            }
        }
        {
            uint32_t ab[2][4], as_r[2][4];
            #pragma unroll
            for (int mt = 0; mt < 2; mt++) {
                int row = wm * 32 + mt * 16 + gq;
                ab[mt][0]   = AsB[buf][cq][row];     ab[mt][1]   = AsB[buf][cq][row + 8];
                ab[mt][2]   = AsB[buf][cq + 4][row]; ab[mt][3]   = AsB[buf][cq + 4][row + 8];
                as_r[mt][0] = AsS[buf][cq][row];     as_r[mt][1] = AsS[buf][cq][row + 8];
                as_r[mt][2] = AsS[buf][cq + 4][row]; as_r[mt][3] = AsS[buf][cq + 4][row + 8];
            }
            uint32_t bb[4][2], bs[4][2];
            #pragma unroll
            for (int nt = 0; nt < 4; nt++) {
                int col = wn * 32 + nt * 8 + gq;
                bb[nt][0] = BsB[buf][cq][col]; bb[nt][1] = BsB[buf][cq + 4][col];
                bs[nt][0] = BsS[buf][cq][col]; bs[nt][1] = BsS[buf][cq + 4][col];
            }
            #pragma unroll
            for (int mt = 0; mt < 2; mt++)
                #pragma unroll
                for (int nt = 0; nt < 4; nt++) {
                    mma_f16(acc[mt][nt], as_r[mt], bb[nt]);
                    mma_f16(acc[mt][nt], ab[mt],   bs[nt]);
                    mma_f16(acc[mt][nt], ab[mt],   bb[nt]);
                }
        }
        if (tile + 1 < nTiles) {
            __syncthreads();
            int nb = buf ^ 1;
            #pragma unroll
            for (int u = 0; u < ALD; u++) {
                int i = t + 256 * u;
                int r = i >> 3, kp = i & 7;
                AsB[nb][kp][r] = rabg[u]; AsS[nb][kp][r] = rasm[u];
            }
            #pragma unroll
            for (int u = 0; u < BLD; u++) {
                int i = t + 256 * u;
                int col = i % BN, kp = i / BN;
                BsB[nb][kp][col] = rbbg[u]; BsS[nb][kp][col] = rbsm[u];
            }
            __syncthreads();
        }
    }
    #pragma unroll
    for (int mt = 0; mt < 2; mt++) {
        int row0 = bm + wm * 32 + mt * 16 + gq;
        #pragma unroll
        for (int nt = 0; nt < 4; nt++) {
            int col = bn + wn * 32 + nt * 8 + 2 * cq;
            if (row0 < M)
                *(__half2*)&Cm[(long)row0 * Nc + col] =
                    __floats2half2_rn(acc[mt][nt][0], acc[mt][nt][1]);
            if (row0 + 8 < M)
                *(__half2*)&Cm[(long)(row0 + 8) * Nc + col] =
                    __floats2half2_rn(acc[mt][nt][2], acc[mt][nt][3]);
        }
        #pragma unroll
        for (int m = 0; m < 2; m++) {
            float sl = 0.f, dl = 0.f, sh = 0.f, dh = 0.f;
            #pragma unroll
            for (int p = 0; p < 2; p++) {
                int nt = 2 * m + p;
                int cl = wn * 32 + nt * 8 + 2 * cq;
                float a0 = sAS[cl], a1 = sAS[cl + 1];
                float b0 = sAD[cl], b1 = sAD[cl + 1];
                sl += acc[mt][nt][0] * a0 + acc[mt][nt][1] * a1;
                dl += acc[mt][nt][0] * b0 + acc[mt][nt][1] * b1;
                sh += acc[mt][nt][2] * a0 + acc[mt][nt][3] * a1;
                dh += acc[mt][nt][2] * b0 + acc[mt][nt][3] * b1;
            }
            sl += __shfl_xor_sync(FULL, sl, 1); sl += __shfl_xor_sync(FULL, sl, 2);
            dl += __shfl_xor_sync(FULL, dl, 1); dl += __shfl_xor_sync(FULL, dl, 2);
            sh += __shfl_xor_sync(FULL, sh, 1); sh += __shfl_xor_sync(FULL, sh, 2);
            dh += __shfl_xor_sync(FULL, dh, 1); dh += __shfl_xor_sync(FULL, dh, 2);
            if (cq == 0) {
                int hg = bn / C1 + 2 * wn + m;
                if (row0 < M)     { s_[(long)row0 * H1 + hg] = sl; d_[(long)row0 * H1 + hg] = dl; }
                if (row0 + 8 < M) { s_[(long)(row0 + 8) * H1 + hg] = sh; d_[(long)(row0 + 8) * H1 + hg] = dh; }
            }
        }
    }
}

// Layer 2: fp16 A exact (from x1h), B planes pre-split -> 2-term MMA.
// Fused attn epilogue (C2=8: one head per nt).
template <int BM, int BN, int BK>
__global__ void __launch_bounds__(256)
k_gemm_h16(const __half* __restrict__ A,
           const uint32_t* __restrict__ Bb, const uint32_t* __restrict__ Bs_,
           __half* __restrict__ Cm, int M, int K, int Nc,
           const float* __restrict__ aS, const float* __restrict__ aD,
           float* __restrict__ s_, float* __restrict__ d_) {
    constexpr int KP  = BK / 2;
    constexpr int AST = BM + 8;
    constexpr int BST = BN + 8;
    __shared__ uint32_t AsB[2][KP][AST];
    __shared__ uint32_t BsB[2][KP][BST], BsS[2][KP][BST];
    __shared__ float sAS[BN], sAD[BN];
    constexpr int ALD = BM * KP / 256;
    constexpr int BLD = BN * KP / 256;
    int t = threadIdx.x;
    int lane = t & 31, wid = t >> 5;
    int wm = wid & 3, wn = wid >> 2;
    int cq = lane & 3, gq = lane >> 2;
    int bm = blockIdx.y * BM, bn = blockIdx.x * BN;
    float acc[2][4][4] = {};
    uint32_t rabg[ALD], rbbg[BLD], rbsm[BLD];

    if (t < BN) { sAS[t] = aS[bn + t]; sAD[t] = aD[bn + t]; }

    #pragma unroll
    for (int u = 0; u < ALD; u++) {
        int i = t + 256 * u;
        int r = i >> 3, kp = i & 7;
        int row = bm + r;
        AsB[0][kp][r] = (row < M) ? *(const uint32_t*)&A[(long)row * K + 2 * kp] : 0u;
    }
    #pragma unroll
    for (int u = 0; u < BLD; u++) {
        int i = t + 256 * u;
        int col = i % BN, kp = i / BN;
        long o = (long)kp * Nc + bn + col;
        BsB[0][kp][col] = Bb[o];
        BsS[0][kp][col] = Bs_[o];
    }
    __syncthreads();

    int nTiles = K / BK;
    for (int tile = 0; tile < nTiles; tile++) {
        int buf = tile & 1;
        int kpb = (tile + 1) * KP;
        if (tile + 1 < nTiles) {
            #pragma unroll
            for (int u = 0; u < ALD; u++) {
                int i = t + 256 * u;
                int r = i >> 3, kp = i & 7;
                int row = bm + r;
                rabg[u] = (row < M) ? *(const uint32_t*)&A[(long)row * K + 2 * (kpb + kp)] : 0u;
            }
            #pragma unroll
            for (int u = 0; u < BLD; u++) {
                int i = t + 256 * u;
                int col = i % BN, kp = i / BN;
                long o = (long)(kpb + kp) * Nc + bn + col;
                rbbg[u] = Bb[o];
                rbsm[u] = Bs_[o];
            }
        }
        {
            uint32_t ab[2][4];
            #pragma unroll
            for (int mt = 0; mt < 2; mt++) {
                int row = wm * 32 + mt * 16 + gq;
                ab[mt][0] = AsB[buf][cq][row];     ab[mt][1] = AsB[buf][cq][row + 8];
                ab[mt][2] = AsB[buf][cq + 4][row]; ab[mt][3] = AsB[buf][cq + 4][row + 8];
            }
            uint32_t bb[4][2], bs[4][2];
            #pragma unroll
            for (int nt = 0; nt < 4; nt++) {
                int col = wn * 32 + nt * 8 + gq;
                bb[nt][0] = BsB[buf][cq][col]; bb[nt][1] = BsB[buf][cq + 4][col];
                bs[nt][0] = BsS[buf][cq][col]; bs[nt][1] = BsS[buf][cq + 4][col];
            }
            #pragma unroll
            for (int mt = 0; mt < 2; mt++)
                #pragma unroll
                for (int nt = 0; nt < 4; nt++) {
                    mma_f16(acc[mt][nt], ab[mt], bs[nt]);
                    mma_f16(acc[mt][nt], ab[mt], bb[nt]);
                }
        }
        if (tile + 1 < nTiles) {
            __syncthreads();
            int nb = buf ^ 1;
            #pragma unroll
            for (int u = 0; u < ALD; u++) {
                int i = t + 256 * u;
                int r = i >> 3, kp = i & 7;
                AsB[nb][kp][r] = rabg[u];
            }
            #pragma unroll
            for (int u = 0; u < BLD; u++) {
                int i = t + 256 * u;
                int col = i % BN, kp = i / BN;
                BsB[nb][kp][col] = rbbg[u]; BsS[nb][kp][col] = rbsm[u];
            }
            __syncthreads();
        }
    }
    #pragma unroll
    for (int mt = 0; mt < 2; mt++) {
        int row0 = bm + wm * 32 + mt * 16 + gq;
        #pragma unroll
        for (int nt = 0; nt < 4; nt++) {
            int col = bn + wn * 32 + nt * 8 + 2 * cq;
            if (row0 < M)
                *(__half2*)&Cm[(long)row0 * Nc + col] =
                    __floats2half2_rn(acc[mt][nt][0], acc[mt][nt][1]);
            if (row0 + 8 < M)
                *(__half2*)&Cm[(long)(row0 + 8) * Nc + col] =
                    __floats2half2_rn(acc[mt][nt][2], acc[mt][nt][3]);
            int cl = wn * 32 + nt * 8 + 2 * cq;
            float a0 = sAS[cl], a1 = sAS[cl + 1];
            float b0 = sAD[cl], b1 = sAD[cl + 1];
            float sl = acc[mt][nt][0] * a0 + acc[mt][nt][1] * a1;
            float dl = acc[mt][nt][0] * b0 + acc[mt][nt][1] * b1;
            float sh = acc[mt][nt][2] * a0 + acc[mt][nt][3] * a1;
            float dh = acc[mt][nt][2] * b0 + acc[mt][nt][3] * b1;
            sl += __shfl_xor_sync(FULL, sl, 1); sl += __shfl_xor_sync(FULL, sl, 2);
            dl += __shfl_xor_sync(FULL, dl, 1); dl += __shfl_xor_sync(FULL, dl, 2);
            sh += __shfl_xor_sync(FULL, sh, 1); sh += __shfl_xor_sync(FULL, sh, 2);
            dh += __shfl_xor_sync(FULL, dh, 1); dh += __shfl_xor_sync(FULL, dh, 2);
            if (cq == 0) {
                int hg = bn / C2 + 4 * wn + nt;
                if (row0 < M)     { s_[(long)row0 * H2 + hg] = sl; d_[(long)row0 * H2 + hg] = dl; }
                if (row0 + 8 < M) { s_[(long)(row0 + 8) * H2 + hg] = sh; d_[(long)(row0 + 8) * H2 + hg] = dh; }
            }
        }
    }
}

// ---------------- layer-1 aggregation (R11 version, non-pipelined) ----------
__device__ __forceinline__ void acc8(float* acc, uint4 v, float w) {
    __half2* hv = reinterpret_cast<__half2*>(&v);
    #pragma unroll
    for (int q = 0; q < 4; q++) {
        float2 f = __half22float2(hv[q]);
        acc[2 * q]     += w * f.x;
        acc[2 * q + 1] += w * f.y;
    }
}

__global__ void k_agg1(const __half* __restrict__ h, const float* __restrict__ as_,
                       const float* __restrict__ ad_, const float* __restrict__ bias,
                       __half* __restrict__ out, int n0, int cnt) {
    constexpr int H = H1, D = D1;
    int warp = (blockIdx.x * blockDim.x + threadIdx.x) >> 5;
    int lane = threadIdx.x & 31;
    if (warp >= cnt) return;
    int node = n0 + warp;
    int r0 = g_rowptr[node];
    int r1 = g_rowptr[node + 1];

    float adv = (lane < H) ? ad_[node * H + lane] : 0.f;
    int myHead = (lane < 24) ? (lane >> 1) : 0;

    float acc[8] = {};
    float denom = 0.f;

    // implicit self-loop
    {
        float wS = (lane < H) ? __expf(leaky(__ldg(as_ + (long)node * H + lane) + adv)) : 0.f;
        denom += wS;
        float eS = __shfl_sync(FULL, wS, myHead);
        if (lane < 24) {
            uint4 v = *(const uint4*)(h + (long)node * D + lane * 8);
            acc8(acc, v, eS);
        }
    }

    int j = r0;
    for (; j + 3 < r1; j += 4) {
        int s0 = g_col[j], s1 = g_col[j + 1], s2 = g_col[j + 2], s3 = g_col[j + 3];
        float w0 = 0.f, w1 = 0.f, w2 = 0.f, w3 = 0.f;
        if (lane < H) {
            w0 = __expf(leaky(__ldg(as_ + (long)s0 * H + lane) + adv));
            w1 = __expf(leaky(__ldg(as_ + (long)s1 * H + lane) + adv));
            w2 = __expf(leaky(__ldg(as_ + (long)s2 * H + lane) + adv));
            w3 = __expf(leaky(__ldg(as_ + (long)s3 * H + lane) + adv));
            denom += (w0 + w1) + (w2 + w3);
        }
        float e0 = __shfl_sync(FULL, w0, myHead);
        float e1 = __shfl_sync(FULL, w1, myHead);
        float e2 = __shfl_sync(FULL, w2, myHead);
        float e3 = __shfl_sync(FULL, w3, myHead);
        if (lane < 24) {
            uint4 v0 = *(const uint4*)(h + (long)s0 * D + lane * 8);
            uint4 v1 = *(const uint4*)(h + (long)s1 * D + lane * 8);
            uint4 v2 = *(const uint4*)(h + (long)s2 * D + lane * 8);
            uint4 v3 = *(const uint4*)(h + (long)s3 * D + lane * 8);
            acc8(acc, v0, e0);
            acc8(acc, v1, e1);
            acc8(acc, v2, e2);
            acc8(acc, v3, e3);
        }
    }
    for (; j < r1; j++) {
        int s0 = g_col[j];
        float w0 = 0.f;
        if (lane < H) {
            w0 = __expf(leaky(__ldg(as_ + (long)s0 * H + lane) + adv));
            denom += w0;
        }
        float e0 = __shfl_sync(FULL, w0, myHead);
        if (lane < 24) {
            uint4 v0 = *(const uint4*)(h + (long)s0 * D + lane * 8);
            acc8(acc, v0, e0);
        }
    }

    float rden = __frcp_rn(denom);
    float rk = __shfl_sync(FULL, rden, myHead);
    if (lane < 24) {
        int off = lane * 8;
        const float4* bp = (const float4*)&bias[off];
        float4 b0 = bp[0], b1 = bp[1];
        float v[8];
        v[0] = acc[0] * rk + b0.x; v[1] = acc[1] * rk + b0.y;
        v[2] = acc[2] * rk + b0.z; v[3] = acc[3] * rk + b0.w;
        v[4] = acc[4] * rk + b1.x; v[5] = acc[5] * rk + b1.y;
        v[6] = acc[6] * rk + b1.z; v[7] = acc[7] * rk + b1.w;
        #pragma unroll
        for (int q = 0; q < 8; q++)
            v[q] = v[q] > 0.f ? v[q] : __expf(v[q]) - 1.f;
        uint4 pk;
        __half2* ph = reinterpret_cast<__half2*>(&pk);
        ph[0] = __floats2half2_rn(v[0], v[1]);
        ph[1] = __floats2half2_rn(v[2], v[3]);
        ph[2] = __floats2half2_rn(v[4], v[5]);
        ph[3] = __floats2half2_rn(v[6], v[7]);
        *(uint4*)(out + (long)node * D + off) = pk;
    }
}

// ---------------- layer-2 aggregation (R11 version) --------------------------
template <int H, int C>
__global__ void k_agg(const __half* __restrict__ h, const float* __restrict__ as_,
                      const float* __restrict__ ad_, const float* __restrict__ bias,
                      float* __restrict__ out, int n0, int cnt) {
    constexpr int D = H * C;
    constexpr int PER2 = D / 64;
    int warp = (blockIdx.x * blockDim.x + threadIdx.x) >> 5;
    int lane = threadIdx.x & 31;
    if (warp >= cnt) return;
    int node = n0 + warp;
    int r0 = g_rowptr[node];
    int r1 = g_rowptr[node + 1];

    float adv = (lane < H) ? ad_[node * H + lane] : 0.f;

    float2 acc[PER2];
    #pragma unroll
    for (int i = 0; i < PER2; i++) acc[i] = make_float2(0.f, 0.f);
    float denom = 0.f;

    // implicit self-loop
    {
        float wS = 0.f;
        if (lane < H) {
            wS = __expf(leaky(__ldg(as_ + (long)node * H + lane) + adv));
            denom = wS;
        }
        const __half2* hp = (const __half2*)(h + (long)node * D);
        #pragma unroll
        for (int i = 0; i < PER2; i++) {
            int k2 = 2 * lane + 64 * i;
            int p  = lane + 32 * i;
            float wa = __shfl_sync(FULL, wS, k2 / C);
            float2 v0 = __half22float2(hp[p]);
            acc[i].x += wa * v0.x;
            acc[i].y += wa * v0.y;
        }
    }

    int j = r0;
    for (; j + 3 < r1; j += 4) {
        int s0 = g_col[j], s1 = g_col[j + 1], s2 = g_col[j + 2], s3 = g_col[j + 3];
        float w0 = 0.f, w1 = 0.f, w2 = 0.f, w3 = 0.f;
        if (lane < H) {
            w0 = __expf(leaky(__ldg(as_ + (long)s0 * H + lane) + adv));
            w1 = __expf(leaky(__ldg(as_ + (long)s1 * H + lane) + adv));
            w2 = __expf(leaky(__ldg(as_ + (long)s2 * H + lane) + adv));
            w3 = __expf(leaky(__ldg(as_ + (long)s3 * H + lane) + adv));
            denom += (w0 + w1) + (w2 + w3);
        }
        const __half2* h0 = (const __half2*)(h + (long)s0 * D);
        const __half2* h1 = (const __half2*)(h + (long)s1 * D);
        const __half2* h2 = (const __half2*)(h + (long)s2 * D);
        const __half2* h3 = (const __half2*)(h + (long)s3 * D);
        #pragma unroll
        for (int i = 0; i < PER2; i++) {
            int k2 = 2 * lane + 64 * i;
            int p  = lane + 32 * i;
            int sl = k2 / C;
            float wa = __shfl_sync(FULL, w0, sl);
            float wb = __shfl_sync(FULL, w1, sl);
            float wc = __shfl_sync(FULL, w2, sl);
            float wd = __shfl_sync(FULL, w3, sl);
            float2 v0 = __half22float2(h0[p]);
            float2 v1 = __half22float2(h1[p]);
            float2 v2 = __half22float2(h2[p]);
            float2 v3 = __half22float2(h3[p]);
            acc[i].x += wa * v0.x + wb * v1.x + wc * v2.x + wd * v3.x;
            acc[i].y += wa * v0.y + wb * v1.y + wc * v2.y + wd * v3.y;
        }
    }
    for (; j < r1; j++) {
        int s0 = g_col[j];
        float w0 = 0.f;
        if (lane < H) {
            w0 = __expf(leaky(__ldg(as_ + (long)s0 * H + lane) + adv));
            denom += w0;
        }
        const __half2* h0 = (const __half2*)(h + (long)s0 * D);
        #pragma unroll
        for (int i = 0; i < PER2; i++) {
            int k2 = 2 * lane + 64 * i;
            int p  = lane + 32 * i;
            float wa = __shfl_sync(FULL, w0, k2 / C);
            float2 v0 = __half22float2(h0[p]);
            acc[i].x += wa * v0.x;
            acc[i].y += wa * v0.y;
        }
    }

    float rden = __frcp_rn(denom);
    #pragma unroll
    for (int i = 0; i < PER2; i++) {
        int k2 = 2 * lane + 64 * i;
        float rk = __shfl_sync(FULL, rden, k2 / C);
        float2 bv = *(const float2*)&bias[k2];
        float vx = acc[i].x * rk + bv.x;
        float vy = acc[i].y * rk + bv.y;
        vx = vx > 0.f ? vx : __expf(vx) - 1.f;
        vy = vy > 0.f ? vy : __expf(vy) - 1.f;
        *(float2*)&out[(long)node * D + k2] = make_float2(vx, vy);
    }
}

// ---------------- pair scoring head ----------------
__global__ void k_pair(const float* __restrict__ x, const int* __restrict__ n1,
                       const int* __restrict__ n2, const float* __restrict__ linW,
                       const float* __restrict__ linb, float* __restrict__ y) {
    int warp = (blockIdx.x * blockDim.x + threadIdx.x) >> 5;
    int lane = threadIdx.x & 31;
    if (warp >= PAIRS) return;
    int a = n1[warp], b = n2[warp];
    float p0 = 0.f, p1 = 0.f;
    #pragma unroll
    for (int i = 0; i < 4; i++) {
        int k = lane + 32 * i;
        float xv = (k < D2) ? x[(long)a * D2 + k] : x[(long)b * D2 + (k - D2)];
        p0 += xv * linW[k * 2 + 0];
        p1 += xv * linW[k * 2 + 1];
    }
    #pragma unroll
    for (int off = 16; off; off >>= 1) {
        p0 += __shfl_xor_sync(FULL, p0, off);
        p1 += __shfl_xor_sync(FULL, p1, off);
    }
    if (lane == 0) {
        float z0 = p0 + linb[0], z1 = p1 + linb[1];
        y[warp * 2 + 0] = 1.f / (1.f + __expf(-z0));
        y[warp * 2 + 1] = 1.f / (1.f + __expf(-z1));
    }
}

// ---------------- launcher ----------------
extern "C" void kernel_launch(void* const* d_in, const int* in_sizes, int n_in,
                              void* d_out, int out_size) {
    const float* features = (const float*)d_in[0];
    const int*   edge_index = (const int*)d_in[1];
    const int*   n1 = (const int*)d_in[2];
    const int*   n2 = (const int*)d_in[3];
    const float* W1 = (const float*)d_in[4];
    const float* attS1 = (const float*)d_in[5];
    const float* attD1 = (const float*)d_in[6];
    const float* b1 = (const float*)d_in[7];
    const float* W2 = (const float*)d_in[8];
    const float* attS2 = (const float*)d_in[9];
    const float* attD2 = (const float*)d_in[10];
    const float* b2 = (const float*)d_in[11];
    const float* linW = (const float*)d_in[12];
    const float* linb = (const float*)d_in[13];

    float* out  = (float*)d_out;
    float* y    = out;
    float* xout = out + PAIRS * 2;

    int E = in_sizes[1] / 2;

    __half *p_h1, *p_x1h, *p_h2;
    float *p_as1, *p_ad1, *p_as2, *p_ad2;
    uint32_t *p_fAb, *p_fAs, *p_w1b, *p_w1s, *p_w2b, *p_w2s;
    int *p_deg, *p_cursor;
    cudaGetSymbolAddress((void**)&p_h1, g_h1);
    cudaGetSymbolAddress((void**)&p_x1h, g_x1h);
    cudaGetSymbolAddress((void**)&p_h2, g_h2);
    cudaGetSymbolAddress((void**)&p_as1, g_as1);
    cudaGetSymbolAddress((void**)&p_ad1, g_ad1);
    cudaGetSymbolAddress((void**)&p_as2, g_as2);
    cudaGetSymbolAddress((void**)&p_ad2, g_ad2);
    cudaGetSymbolAddress((void**)&p_fAb, g_fAb);
    cudaGetSymbolAddress((void**)&p_fAs, g_fAs);
    cudaGetSymbolAddress((void**)&p_w1b, g_w1b);
    cudaGetSymbolAddress((void**)&p_w1s, g_w1s);
    cudaGetSymbolAddress((void**)&p_w2b, g_w2b);
    cudaGetSymbolAddress((void**)&p_w2s, g_w2s);
    cudaGetSymbolAddress((void**)&p_deg, g_deg);
    cudaGetSymbolAddress((void**)&p_cursor, g_cursor);

    static cudaStream_t s2 = nullptr;
    static cudaEvent_t evFork = nullptr, evJoin = nullptr, evA = nullptr, evG = nullptr;
    if (!s2) {
        cudaStreamCreateWithFlags(&s2, cudaStreamNonBlocking);
        cudaEventCreateWithFlags(&evFork, cudaEventDisableTiming);
        cudaEventCreateWithFlags(&evJoin, cudaEventDisableTiming);
        cudaEventCreateWithFlags(&evA, cudaEventDisableTiming);
        cudaEventCreateWithFlags(&evG, cudaEventDisableTiming);
    }

    int e4blocks = ((E + 3) / 4 + 255) / 256;

    // fork: CSR build on s2 overlaps splits + GEMM1 on main stream
    cudaEventRecord(evFork, 0);
    cudaStreamWaitEvent(s2, evFork, 0);

    cudaMemsetAsync(p_deg, 0, NN * sizeof(int), s2);
    cudaMemsetAsync(p_cursor, 0, NN * sizeof(int), s2);
    k_count<<<e4blocks, 256, 0, s2>>>(edge_index, E);
    k_scan<<<1, 1024, 0, s2>>>();
    k_scatter<<<e4blocks, 256, 0, s2>>>(edge_index, E);
    cudaEventRecord(evJoin, s2);

    // pre-split operands (once), then GEMM1 with fused attn
    k_split_feat<<<(int)(((long)NN * AKP1 + 255) / 256), 256>>>(features);
    k_split_w1<<<(AKP1 * D1 + 255) / 256, 256>>>(W1);
    k_split_w2<<<(KP2 * D2 + 255) / 256, 256>>>(W2);
    {
        dim3 grid(D1 / 64, (NN + 127) / 128);
        k_gemm_hs<128, 64><<<grid, 256>>>(p_fAb, p_fAs, p_w1b, p_w1s, p_h1,
                                          NN, AKP1, D1,
                                          attS1, attD1, p_as1, p_ad1);
    }

    cudaStreamWaitEvent(0, evJoin, 0);

    // agg1 lo half, then pipeline: GEMM2-lo on s2 overlaps agg1 hi half
    k_agg1<<<(NHALF * 32 + 255) / 256, 256>>>(p_h1, p_as1, p_ad1, b1, p_x1h, 0, NHALF);
    cudaEventRecord(evA, 0);
    cudaStreamWaitEvent(s2, evA, 0);
    {
        dim3 grid(D2 / 64, NHALF / 128);
        k_gemm_h16<128, 64, 16><<<grid, 256, 0, s2>>>(p_x1h, p_w2b, p_w2s, p_h2,
                                                      NHALF, D1, D2,
                                                      attS2, attD2, p_as2, p_ad2);
    }
    cudaEventRecord(evG, s2);

    k_agg1<<<((NN - NHALF) * 32 + 255) / 256, 256>>>(p_h1, p_as1, p_ad1, b1, p_x1h, NHALF, NN - NHALF);
    {
        dim3 grid(D2 / 64, (NN - NHALF + 127) / 128);
        k_gemm_h16<128, 64, 16><<<grid, 256>>>(p_x1h + (long)NHALF * D1, p_w2b, p_w2s,
                                               p_h2 + (long)NHALF * D2, NN - NHALF, D1, D2,
                                               attS2, attD2,
                                               p_as2 + (long)NHALF * H2, p_ad2 + (long)NHALF * H2);
    }
    cudaStreamWaitEvent(0, evG, 0);

    k_agg<H2, C2><<<(NN * 32 + 255) / 256, 256>>>(p_h2, p_as2, p_ad2, b2, xout, 0, NN);

    // Pair head
    k_pair<<<(PAIRS * 32 + 255) / 256, 256>>>(xout, n1, n2, linW, linb, y);
}

// round 14
// speedup vs baseline: 1.3552x; 1.0006x over previous
#include <cuda_runtime.h>
#include <cuda_fp16.h>
#include <cstdint>

#define FULL 0xffffffffu

constexpr int NN   = 50000;
constexpr int FEA  = 213;
constexpr int H1   = 12, C1 = 16, D1 = 192;
constexpr int H2   = 8,  C2 = 8,  D2 = 64;
constexpr int PAIRS = 16384;
constexpr int EMAX = 800000;
constexpr int NHALF = 25088;
constexpr int AKP1 = 112;   // padded k-pair count for K=213 (14 tiles x 8)
constexpr int KP2  = 96;    // k-pairs for K=192

// ---------------- device scratch ----------------
__device__ __half g_h1[NN * D1];
__device__ __half g_x1h[NN * D1];
__device__ __half g_h2[NN * D2];
__device__ float  g_as1[NN * H1];
__device__ float  g_ad1[NN * H1];
__device__ float  g_as2[NN * H2];
__device__ float  g_ad2[NN * H2];
__device__ __align__(16) uint32_t g_fAb[NN * AKP1];
__device__ __align__(16) uint32_t g_fAs[NN * AKP1];
__device__ uint32_t g_w1b[AKP1 * D1], g_w1s[AKP1 * D1];
__device__ uint32_t g_w2b[KP2 * D2],  g_w2s[KP2 * D2];
__device__ __align__(16) int g_deg[NN];
__device__ int    g_cursor[NN];
__device__ int    g_rowptr[NN + 1];
__device__ int    g_col[EMAX];

__device__ __forceinline__ float leaky(float x) { return x > 0.f ? x : 0.2f * x; }

// ---------------- CSR build (edges only; self-loops implicit) ---------------
__global__ void k_count(const int* __restrict__ ei, int E) {
    int i4 = (blockIdx.x * blockDim.x + threadIdx.x) * 4;
    if (i4 + 3 < E) {
        int4 d = *(const int4*)(ei + E + i4);
        atomicAdd(&g_deg[d.x], 1);
        atomicAdd(&g_deg[d.y], 1);
        atomicAdd(&g_deg[d.z], 1);
        atomicAdd(&g_deg[d.w], 1);
    } else {
        for (int i = i4; i < E; i++) atomicAdd(&g_deg[ei[E + i]], 1);
    }
}

__global__ void k_scan() {
    __shared__ int s[1024];
    int t = threadIdx.x;
    const int chunk = 52;
    int start = t * chunk;
    int end = start + chunk; if (end > NN) end = NN; if (start > NN) start = NN;
    int sum = 0;
    if (start < NN) {
        int full = (end - start) / 4;
        const int4* p = (const int4*)(g_deg + start);
        for (int i = 0; i < full; i++) { int4 v = p[i]; sum += v.x + v.y + v.z + v.w; }
        for (int i = start + full * 4; i < end; i++) sum += g_deg[i];
    }
    s[t] = sum;
    __syncthreads();
    for (int off = 1; off < 1024; off <<= 1) {
        int v = 0;
        if (t >= off) v = s[t - off];
        __syncthreads();
        s[t] += v;
        __syncthreads();
    }
    int run = s[t] - sum;
    for (int i = start; i < end; i++) { g_rowptr[i] = run; run += g_deg[i]; }
    if (t == 1023) g_rowptr[NN] = s[1023];
}

__global__ void k_scatter(const int* __restrict__ ei, int E) {
    int i4 = (blockIdx.x * blockDim.x + threadIdx.x) * 4;
    if (i4 + 3 < E) {
        int4 sv = *(const int4*)(ei + i4);
        int4 dv = *(const int4*)(ei + E + i4);
        int p0 = atomicAdd(&g_cursor[dv.x], 1); g_col[g_rowptr[dv.x] + p0] = sv.x;
        int p1 = atomicAdd(&g_cursor[dv.y], 1); g_col[g_rowptr[dv.y] + p1] = sv.y;
        int p2 = atomicAdd(&g_cursor[dv.z], 1); g_col[g_rowptr[dv.z] + p2] = sv.z;
        int p3 = atomicAdd(&g_cursor[dv.w], 1); g_col[g_rowptr[dv.w] + p3] = sv.w;
    } else {
        for (int i = i4; i < E; i++) {
            int src = ei[i], dst = ei[E + i];
            int pos = atomicAdd(&g_cursor[dst], 1);
            g_col[g_rowptr[dst] + pos] = src;
        }
    }
}

// ---------------- operand pre-split (Markidis big/small, done once) ----------
__device__ __forceinline__ void split_pair(float x0, float x1,
                                           uint32_t& bg, uint32_t& sm) {
    __half2 b = __floats2half2_rn(x0, x1);
    float2 bf = __half22float2(b);
    __half2 s = __floats2half2_rn(x0 - bf.x, x1 - bf.y);
    bg = *reinterpret_cast<uint32_t*>(&b);
    sm = *reinterpret_cast<uint32_t*>(&s);
}

// vectorized: each thread converts 4 k-pairs (8 floats) of one row,
// stores one uint4 to each plane.
__global__ void k_split_feat(const float* __restrict__ f) {
    long idx = (long)blockIdx.x * blockDim.x + threadIdx.x;
    if (idx >= (long)NN * (AKP1 / 4)) return;
    int row = idx / (AKP1 / 4), q = idx % (AKP1 / 4);
    int k0 = 8 * q;
    const float* fp = f + (long)row * FEA;
    float x[8];
    #pragma unroll
    for (int i = 0; i < 8; i++)
        x[i] = (k0 + i < FEA) ? fp[k0 + i] : 0.f;
    uint4 bg, sm;
    split_pair(x[0], x[1], bg.x, sm.x);
    split_pair(x[2], x[3], bg.y, sm.y);
    split_pair(x[4], x[5], bg.z, sm.z);
    split_pair(x[6], x[7], bg.w, sm.w);
    long o = (long)row * AKP1 + 4 * q;
    *(uint4*)(g_fAb + o) = bg;
    *(uint4*)(g_fAs + o) = sm;
}

__global__ void k_split_w1(const float* __restrict__ w) {
    int idx = blockIdx.x * blockDim.x + threadIdx.x;
    if (idx >= AKP1 * D1) return;
    int kp = idx / D1, col = idx % D1;
    int k0 = 2 * kp;
    float x0 = (k0     < FEA) ? w[(long)k0       * D1 + col] : 0.f;
    float x1 = (k0 + 1 < FEA) ? w[(long)(k0 + 1) * D1 + col] : 0.f;
    split_pair(x0, x1, g_w1b[idx], g_w1s[idx]);
}

__global__ void k_split_w2(const float* __restrict__ w) {
    int idx = blockIdx.x * blockDim.x + threadIdx.x;
    if (idx >= KP2 * D2) return;
    int kp = idx / D2, col = idx % D2;
    int k0 = 2 * kp;
    float x0 = w[(long)k0       * D2 + col];
    float x1 = w[(long)(k0 + 1) * D2 + col];
    split_pair(x0, x1, g_w2b[idx], g_w2s[idx]);
}

// ------------- fp16-split tensor-core GEMM, m16n8k16, pre-split loads -------
__device__ __forceinline__ void mma_f16(float* c, const uint32_t* a, const uint32_t* b) {
    asm volatile(
        "mma.sync.aligned.m16n8k16.row.col.f32.f16.f16.f32 "
        "{%0,%1,%2,%3}, {%4,%5,%6,%7}, {%8,%9}, {%0,%1,%2,%3};"
        : "+f"(c[0]), "+f"(c[1]), "+f"(c[2]), "+f"(c[3])
        : "r"(a[0]), "r"(a[1]), "r"(a[2]), "r"(a[3]), "r"(b[0]), "r"(b[1]));
}

// Layer 1: A planes [M][AKP], B planes [AKP][Nc]; 3-term split MMA.
// Fused attention epilogue (C1=16: 2 heads/warp). Pure LDG loads, no cvt.
template <int BM, int BN>
__global__ void __launch_bounds__(256)
k_gemm_hs(const uint32_t* __restrict__ Ab, const uint32_t* __restrict__ As_,
          const uint32_t* __restrict__ Bb, const uint32_t* __restrict__ Bs_,
          __half* __restrict__ Cm, int M, int AKP, int Nc,
          const float* __restrict__ aS, const float* __restrict__ aD,
          float* __restrict__ s_, float* __restrict__ d_) {
    constexpr int KP  = 8;
    constexpr int AST = BM + 8;
    constexpr int BST = BN + 8;
    __shared__ uint32_t AsB[2][KP][AST], AsS[2][KP][AST];
    __shared__ uint32_t BsB[2][KP][BST], BsS[2][KP][BST];
    __shared__ float sAS[BN], sAD[BN];
    constexpr int ALD = BM * KP / 256;   // 4
    constexpr int BLD = BN * KP / 256;   // 2
    int t = threadIdx.x;
    int lane = t & 31, wid = t >> 5;
    int wm = wid & 3, wn = wid >> 2;
    int cq = lane & 3, gq = lane >> 2;
    int bm = blockIdx.y * BM, bn = blockIdx.x * BN;
    float acc[2][4][4] = {};
    uint32_t rabg[ALD], rasm[ALD], rbbg[BLD], rbsm[BLD];

    if (t < BN) { sAS[t] = aS[bn + t]; sAD[t] = aD[bn + t]; }

    #pragma unroll
    for (int u = 0; u < ALD; u++) {
        int i = t + 256 * u;
        int r = i >> 3, kp = i & 7;
        int row = bm + r;
        long o = (long)row * AKP + kp;
        AsB[0][kp][r] = (row < M) ? Ab[o] : 0u;
        AsS[0][kp][r] = (row < M) ? As_[o] : 0u;
    }
    #pragma unroll
    for (int u = 0; u < BLD; u++) {
        int i = t + 256 * u;
        int col = i % BN, kp = i / BN;
        long o = (long)kp * Nc + bn + col;
        BsB[0][kp][col] = Bb[o];
        BsS[0][kp][col] = Bs_[o];
    }
    __syncthreads();

    int nTiles = AKP / KP;
    for (int tile = 0; tile < nTiles; tile++) {
        int buf = tile & 1;
        int kbase = (tile + 1) * KP;
        if (tile + 1 < nTiles) {
            #pragma unroll
            for (int u = 0; u < ALD; u++) {
                int i = t + 256 * u;
                int r = i >> 3, kp = i & 7;
                int row = bm + r;
                long o = (long)row * AKP + kbase + kp;
                rabg[u] = (row < M) ? Ab[o] : 0u;
                rasm[u] = (row < M) ? As_[o] : 0u;
            }
            #pragma unroll
            for (int u = 0; u < BLD; u++) {
                int i = t + 256 * u;
                int col = i % BN, kp = i / BN;
                long o = (long)(kbase + kp) * Nc + bn + col;
                rbbg[u] = Bb[o];
                rbsm[u] = Bs_[o];
            }
        }
        {
            uint32_t ab[2][4], as_r[2][4];
            #pragma unroll
            for (int mt = 0; mt < 2; mt++) {
                int row = wm * 32 + mt * 16 + gq;
                ab[mt][0]   = AsB[buf][cq][row];     ab[mt][1]   = AsB[buf][cq][row + 8];
                ab[mt][2]   = AsB[buf][cq + 4][row]; ab[mt][3]   = AsB[buf][cq + 4][row + 8];
                as_r[mt][0] = AsS[buf][cq][row];     as_r[mt][1] = AsS[buf][cq][row + 8];
                as_r[mt][2] = AsS[buf][cq + 4][row]; as_r[mt][3] = AsS[buf][cq + 4][row + 8];
            }
            uint32_t bb[4][2], bs[4][2];
            #pragma unroll
            for (int nt = 0; nt < 4; nt++) {
                int col = wn * 32 + nt * 8 + gq;
                bb[nt][0] = BsB[buf][cq][col]; bb[nt][1] = BsB[buf][cq + 4][col];
                bs[nt][0] = BsS[buf][cq][col]; bs[nt][1] = BsS[buf][cq + 4][col];
            }
            #pragma unroll
            for (int mt = 0; mt < 2; mt++)
                #pragma unroll
                for (int nt = 0; nt < 4; nt++) {
                    mma_f16(acc[mt][nt], as_r[mt], bb[nt]);
                    mma_f16(acc[mt][nt], ab[mt],   bs[nt]);
                    mma_f16(acc[mt][nt], ab[mt],   bb[nt]);
                }
        }
        if (tile + 1 < nTiles) {
            __syncthreads();
            int nb = buf ^ 1;
            #pragma unroll
            for (int u = 0; u < ALD; u++) {
                int i = t + 256 * u;
                int r = i >> 3, kp = i & 7;
                AsB[nb][kp][r] = rabg[u]; AsS[nb][kp][r] = rasm[u];
            }
            #pragma unroll
            for (int u = 0; u < BLD; u++) {
                int i = t + 256 * u;
                int col = i % BN, kp = i / BN;
                BsB[nb][kp][col] = rbbg[u]; BsS[nb][kp][col] = rbsm[u];
            }
            __syncthreads();
        }
    }
    #pragma unroll
    for (int mt = 0; mt < 2; mt++) {
        int row0 = bm + wm * 32 + mt * 16 + gq;
        #pragma unroll
        for (int nt = 0; nt < 4; nt++) {
            int col = bn + wn * 32 + nt * 8 + 2 * cq;
            if (row0 < M)
                *(__half2*)&Cm[(long)row0 * Nc + col] =
                    __floats2half2_rn(acc[mt][nt][0], acc[mt][nt][1]);
            if (row0 + 8 < M)
                *(__half2*)&Cm[(long)(row0 + 8) * Nc + col] =
                    __floats2half2_rn(acc[mt][nt][2], acc[mt][nt][3]);
        }
        #pragma unroll
        for (int m = 0; m < 2; m++) {
            float sl = 0.f, dl = 0.f, sh = 0.f, dh = 0.f;
            #pragma unroll
            for (int p = 0; p < 2; p++) {
                int nt = 2 * m + p;
                int cl = wn * 32 + nt * 8 + 2 * cq;
                float a0 = sAS[cl], a1 = sAS[cl + 1];
                float b0 = sAD[cl], b1 = sAD[cl + 1];
                sl += acc[mt][nt][0] * a0 + acc[mt][nt][1] * a1;
                dl += acc[mt][nt][0] * b0 + acc[mt][nt][1] * b1;
                sh += acc[mt][nt][2] * a0 + acc[mt][nt][3] * a1;
                dh += acc[mt][nt][2] * b0 + acc[mt][nt][3] * b1;
            }
            sl += __shfl_xor_sync(FULL, sl, 1); sl += __shfl_xor_sync(FULL, sl, 2);
            dl += __shfl_xor_sync(FULL, dl, 1); dl += __shfl_xor_sync(FULL, dl, 2);
            sh += __shfl_xor_sync(FULL, sh, 1); sh += __shfl_xor_sync(FULL, sh, 2);
            dh += __shfl_xor_sync(FULL, dh, 1); dh += __shfl_xor_sync(FULL, dh, 2);
            if (cq == 0) {
                int hg = bn / C1 + 2 * wn + m;
                if (row0 < M)     { s_[(long)row0 * H1 + hg] = sl; d_[(long)row0 * H1 + hg] = dl; }
                if (row0 + 8 < M) { s_[(long)(row0 + 8) * H1 + hg] = sh; d_[(long)(row0 + 8) * H1 + hg] = dh; }
            }
        }
    }
}

// Layer 2: fp16 A exact (from x1h), B planes pre-split -> 2-term MMA.
template <int BM, int BN, int BK>
__global__ void __launch_bounds__(256)
k_gemm_h16(const __half* __restrict__ A,
           const uint32_t* __restrict__ Bb, const uint32_t* __restrict__ Bs_,
           __half* __restrict__ Cm, int M, int K, int Nc,
           const float* __restrict__ aS, const float* __restrict__ aD,
           float* __restrict__ s_, float* __restrict__ d_) {
    constexpr int KP  = BK / 2;
    constexpr int AST = BM + 8;
    constexpr int BST = BN + 8;
    __shared__ uint32_t AsB[2][KP][AST];
    __shared__ uint32_t BsB[2][KP][BST], BsS[2][KP][BST];
    __shared__ float sAS[BN], sAD[BN];
    constexpr int ALD = BM * KP / 256;
    constexpr int BLD = BN * KP / 256;
    int t = threadIdx.x;
    int lane = t & 31, wid = t >> 5;
    int wm = wid & 3, wn = wid >> 2;
    int cq = lane & 3, gq = lane >> 2;
    int bm = blockIdx.y * BM, bn = blockIdx.x * BN;
    float acc[2][4][4] = {};
    uint32_t rabg[ALD], rbbg[BLD], rbsm[BLD];

    if (t < BN) { sAS[t] = aS[bn + t]; sAD[t] = aD[bn + t]; }

    #pragma unroll
    for (int u = 0; u < ALD; u++) {
        int i = t + 256 * u;
        int r = i >> 3, kp = i & 7;
        int row = bm + r;
        AsB[0][kp][r] = (row < M) ? *(const uint32_t*)&A[(long)row * K + 2 * kp] : 0u;
    }
    #pragma unroll
    for (int u = 0; u < BLD; u++) {
        int i = t + 256 * u;
        int col = i % BN, kp = i / BN;
        long o = (long)kp * Nc + bn + col;
        BsB[0][kp][col] = Bb[o];
        BsS[0][kp][col] = Bs_[o];
    }
    __syncthreads();

    int nTiles = K / BK;
    for (int tile = 0; tile < nTiles; tile++) {
        int buf = tile & 1;
        int kpb = (tile + 1) * KP;
        if (tile + 1 < nTiles) {
            #pragma unroll
            for (int u = 0; u < ALD; u++) {
                int i = t + 256 * u;
                int r = i >> 3, kp = i & 7;
                int row = bm + r;
                rabg[u] = (row < M) ? *(const uint32_t*)&A[(long)row * K + 2 * (kpb + kp)] : 0u;
            }
            #pragma unroll
            for (int u = 0; u < BLD; u++) {
                int i = t + 256 * u;
                int col = i % BN, kp = i / BN;
                long o = (long)(kpb + kp) * Nc + bn + col;
                rbbg[u] = Bb[o];
                rbsm[u] = Bs_[o];
            }
        }
        {
            uint32_t ab[2][4];
            #pragma unroll
            for (int mt = 0; mt < 2; mt++) {
                int row = wm * 32 + mt * 16 + gq;
                ab[mt][0] = AsB[buf][cq][row];     ab[mt][1] = AsB[buf][cq][row + 8];
                ab[mt][2] = AsB[buf][cq + 4][row]; ab[mt][3] = AsB[buf][cq + 4][row + 8];
            }
            uint32_t bb[4][2], bs[4][2];
            #pragma unroll
            for (int nt = 0; nt < 4; nt++) {
                int col = wn * 32 + nt * 8 + gq;
                bb[nt][0] = BsB[buf][cq][col]; bb[nt][1] = BsB[buf][cq + 4][col];
                bs[nt][0] = BsS[buf][cq][col]; bs[nt][1] = BsS[buf][cq + 4][col];
            }
            #pragma unroll
            for (int mt = 0; mt < 2; mt++)
                #pragma unroll
                for (int nt = 0; nt < 4; nt++) {
                    mma_f16(acc[mt][nt], ab[mt], bs[nt]);
                    mma_f16(acc[mt][nt], ab[mt], bb[nt]);
                }
        }
        if (tile + 1 < nTiles) {
            __syncthreads();
            int nb = buf ^ 1;
            #pragma unroll
            for (int u = 0; u < ALD; u++) {
                int i = t + 256 * u;
                int r = i >> 3, kp = i & 7;
                AsB[nb][kp][r] = rabg[u];
            }
            #pragma unroll
            for (int u = 0; u < BLD; u++) {
                int i = t + 256 * u;
                int col = i % BN, kp = i / BN;
                BsB[nb][kp][col] = rbbg[u]; BsS[nb][kp][col] = rbsm[u];
            }
            __syncthreads();
        }
    }
    #pragma unroll
    for (int mt = 0; mt < 2; mt++) {
        int row0 = bm + wm * 32 + mt * 16 + gq;
        #pragma unroll
        for (int nt = 0; nt < 4; nt++) {
            int col = bn + wn * 32 + nt * 8 + 2 * cq;
            if (row0 < M)
                *(__half2*)&Cm[(long)row0 * Nc + col] =
                    __floats2half2_rn(acc[mt][nt][0], acc[mt][nt][1]);
            if (row0 + 8 < M)
                *(__half2*)&Cm[(long)(row0 + 8) * Nc + col] =
                    __floats2half2_rn(acc[mt][nt][2], acc[mt][nt][3]);
            int cl = wn * 32 + nt * 8 + 2 * cq;
            float a0 = sAS[cl], a1 = sAS[cl + 1];
            float b0 = sAD[cl], b1 = sAD[cl + 1];
            float sl = acc[mt][nt][0] * a0 + acc[mt][nt][1] * a1;
            float dl = acc[mt][nt][0] * b0 + acc[mt][nt][1] * b1;
            float sh = acc[mt][nt][2] * a0 + acc[mt][nt][3] * a1;
            float dh = acc[mt][nt][2] * b0 + acc[mt][nt][3] * b1;
            sl += __shfl_xor_sync(FULL, sl, 1); sl += __shfl_xor_sync(FULL, sl, 2);
            dl += __shfl_xor_sync(FULL, dl, 1); dl += __shfl_xor_sync(FULL, dl, 2);
            sh += __shfl_xor_sync(FULL, sh, 1); sh += __shfl_xor_sync(FULL, sh, 2);
            dh += __shfl_xor_sync(FULL, dh, 1); dh += __shfl_xor_sync(FULL, dh, 2);
            if (cq == 0) {
                int hg = bn / C2 + 4 * wn + nt;
                if (row0 < M)     { s_[(long)row0 * H2 + hg] = sl; d_[(long)row0 * H2 + hg] = dl; }
                if (row0 + 8 < M) { s_[(long)(row0 + 8) * H2 + hg] = sh; d_[(long)(row0 + 8) * H2 + hg] = dh; }
            }
        }
    }
}

// ---------------- layer-1 aggregation: cp.async-staged gather ---------------
__device__ __forceinline__ void acc8(float* acc, uint4 v, float w) {
    __half2* hv = reinterpret_cast<__half2*>(&v);
    #pragma unroll
    for (int q = 0; q < 4; q++) {
        float2 f = __half22float2(hv[q]);
        acc[2 * q]     += w * f.x;
        acc[2 * q + 1] += w * f.y;
    }
}
__device__ __forceinline__ void cp16(uint32_t smem_addr, const void* gptr) {
    asm volatile("cp.async.cg.shared.global [%0], [%1], 16;"
                 :: "r"(smem_addr), "l"(gptr));
}

__global__ void __launch_bounds__(256)
k_agg1(const __half* __restrict__ h, const float* __restrict__ as_,
       const float* __restrict__ ad_, const float* __restrict__ bias,
       __half* __restrict__ out, int n0, int cnt) {
    constexpr int H = H1, D = D1;
    // per-warp staging: 2 stages x 4 rows x 384B
    __shared__ __align__(16) char stage_mem[8][2][4][384];
    int widx = threadIdx.x >> 5;
    int warp = (blockIdx.x * blockDim.x + threadIdx.x) >> 5;
    int lane = threadIdx.x & 31;
    if (warp >= cnt) return;
    int node = n0 + warp;
    int r0 = g_rowptr[node];
    int r1 = g_rowptr[node + 1];

    float adv = (lane < H) ? ad_[node * H + lane] : 0.f;
    int myHead = (lane < 24) ? (lane >> 1) : 0;

    float acc[8] = {};
    float denom = 0.f;

    // implicit self-loop (direct load)
    {
        float wS = (lane < H) ? __expf(leaky(__ldg(as_ + (long)node * H + lane) + adv)) : 0.f;
        denom += wS;
        float eS = __shfl_sync(FULL, wS, myHead);
        if (lane < 24) {
            uint4 v = *(const uint4*)(h + (long)node * D + lane * 8);
            acc8(acc, v, eS);
        }
    }

    uint32_t sbase;
    {
        void* p = &stage_mem[widx][0][0][0];
        asm("{ .reg .u64 tmp; cvta.to.shared.u64 tmp, %1; cvt.u32.u64 %0, tmp; }"
            : "=r"(sbase) : "l"(p));
    }
    // stage offsets: stage s, row r -> sbase + s*1536 + r*384 + lane*16

    int cols[4];
    float av[4];
    auto load_meta = [&](int j) {
        cols[0] = (j     < r1) ? g_col[j]     : node;
        cols[1] = (j + 1 < r1) ? g_col[j + 1] : node;
        cols[2] = (j + 2 < r1) ? g_col[j + 2] : node;
        cols[3] = (j + 3 < r1) ? g_col[j + 3] : node;
        if (lane < H) {
            av[0] = __ldg(as_ + (long)cols[0] * H + lane);
            av[1] = __ldg(as_ + (long)cols[1] * H + lane);
            av[2] = __ldg(as_ + (long)cols[2] * H + lane);
            av[3] = __ldg(as_ + (long)cols[3] * H + lane);
        }
    };
    auto issue_cp = [&](int st) {
        if (lane < 24) {
            #pragma unroll
            for (int r = 0; r < 4; r++)
                cp16(sbase + st * 1536 + r * 384 + lane * 16,
                     h + (long)cols[r] * D + lane * 8);
        }
        asm volatile("cp.async.commit_group;" ::: "memory");
    };

    if (r0 < r1) {
        load_meta(r0);
        issue_cp(0);
    }

    int stage = 0;
    for (int jj = r0; jj < r1; jj += 4) {
        // current group's weights from registers
        float w0 = (lane < H)                ? __expf(leaky(av[0] + adv)) : 0.f;
        float w1 = (lane < H && jj + 1 < r1) ? __expf(leaky(av[1] + adv)) : 0.f;
        float w2 = (lane < H && jj + 2 < r1) ? __expf(leaky(av[2] + adv)) : 0.f;
        float w3 = (lane < H && jj + 3 < r1) ? __expf(leaky(av[3] + adv)) : 0.f;
        // prefetch next group meta + h rows
        int jn = jj + 4;
        if (jn < r1) {
            load_meta(jn);
            issue_cp(stage ^ 1);
        } else {
            asm volatile("cp.async.commit_group;" ::: "memory");
        }
        denom += (w0 + w1) + (w2 + w3);
        float e0 = __shfl_sync(FULL, w0, myHead);
        float e1 = __shfl_sync(FULL, w1, myHead);
        float e2 = __shfl_sync(FULL, w2, myHead);
        float e3 = __shfl_sync(FULL, w3, myHead);
        asm volatile("cp.async.wait_group 1;" ::: "memory");
        if (lane < 24) {
            const char* sp = &stage_mem[widx][stage][0][0] + lane * 16;
            uint4 v0 = *(const uint4*)(sp);
            uint4 v1 = *(const uint4*)(sp + 384);
            uint4 v2 = *(const uint4*)(sp + 768);
            uint4 v3 = *(const uint4*)(sp + 1152);
            acc8(acc, v0, e0);
            acc8(acc, v1, e1);
            acc8(acc, v2, e2);
            acc8(acc, v3, e3);
        }
        stage ^= 1;
    }
    asm volatile("cp.async.wait_group 0;" ::: "memory");

    float rden = __frcp_rn(denom);
    float rk = __shfl_sync(FULL, rden, myHead);
    if (lane < 24) {
        int off = lane * 8;
        const float4* bp = (const float4*)&bias[off];
        float4 b0 = bp[0], b1 = bp[1];
        float v[8];
        v[0] = acc[0] * rk + b0.x; v[1] = acc[1] * rk + b0.y;
        v[2] = acc[2] * rk + b0.z; v[3] = acc[3] * rk + b0.w;
        v[4] = acc[4] * rk + b1.x; v[5] = acc[5] * rk + b1.y;
        v[6] = acc[6] * rk + b1.z; v[7] = acc[7] * rk + b1.w;
        #pragma unroll
        for (int q = 0; q < 8; q++)
            v[q] = v[q] > 0.f ? v[q] : __expf(v[q]) - 1.f;
        uint4 pk;
        __half2* ph = reinterpret_cast<__half2*>(&pk);
        ph[0] = __floats2half2_rn(v[0], v[1]);
        ph[1] = __floats2half2_rn(v[2], v[3]);
        ph[2] = __floats2half2_rn(v[4], v[5]);
        ph[3] = __floats2half2_rn(v[6], v[7]);
        *(uint4*)(out + (long)node * D + off) = pk;
    }
}

// ---------------- layer-2 aggregation (R11 version) --------------------------
template <int H, int C>
__global__ void k_agg(const __half* __restrict__ h, const float* __restrict__ as_,
                      const float* __restrict__ ad_, const float* __restrict__ bias,
                      float* __restrict__ out, int n0, int cnt) {
    constexpr int D = H * C;
    constexpr int PER2 = D / 64;
    int warp = (blockIdx.x * blockDim.x + threadIdx.x) >> 5;
    int lane = threadIdx.x & 31;
    if (warp >= cnt) return;
    int node = n0 + warp;
    int r0 = g_rowptr[node];
    int r1 = g_rowptr[node + 1];

    float adv = (lane < H) ? ad_[node * H + lane] : 0.f;

    float2 acc[PER2];
    #pragma unroll
    for (int i = 0; i < PER2; i++) acc[i] = make_float2(0.f, 0.f);
    float denom = 0.f;

    {
        float wS = 0.f;
        if (lane < H) {
            wS = __expf(leaky(__ldg(as_ + (long)node * H + lane) + adv));
            denom = wS;
        }
        const __half2* hp = (const __half2*)(h + (long)node * D);
        #pragma unroll
        for (int i = 0; i < PER2; i++) {
            int k2 = 2 * lane + 64 * i;
            int p  = lane + 32 * i;
            float wa = __shfl_sync(FULL, wS, k2 / C);
            float2 v0 = __half22float2(hp[p]);
            acc[i].x += wa * v0.x;
            acc[i].y += wa * v0.y;
        }
    }

    int j = r0;
    for (; j + 3 < r1; j += 4) {
        int s0 = g_col[j], s1 = g_col[j + 1], s2 = g_col[j + 2], s3 = g_col[j + 3];
        float w0 = 0.f, w1 = 0.f, w2 = 0.f, w3 = 0.f;
        if (lane < H) {
            w0 = __expf(leaky(__ldg(as_ + (long)s0 * H + lane) + adv));
            w1 = __expf(leaky(__ldg(as_ + (long)s1 * H + lane) + adv));
            w2 = __expf(leaky(__ldg(as_ + (long)s2 * H + lane) + adv));
            w3 = __expf(leaky(__ldg(as_ + (long)s3 * H + lane) + adv));
            denom += (w0 + w1) + (w2 + w3);
        }
        const __half2* h0 = (const __half2*)(h + (long)s0 * D);
        const __half2* h1 = (const __half2*)(h + (long)s1 * D);
        const __half2* h2 = (const __half2*)(h + (long)s2 * D);
        const __half2* h3 = (const __half2*)(h + (long)s3 * D);
        #pragma unroll
        for (int i = 0; i < PER2; i++) {
            int k2 = 2 * lane + 64 * i;
            int p  = lane + 32 * i;
            int sl = k2 / C;
            float wa = __shfl_sync(FULL, w0, sl);
            float wb = __shfl_sync(FULL, w1, sl);
            float wc = __shfl_sync(FULL, w2, sl);
            float wd = __shfl_sync(FULL, w3, sl);
            float2 v0 = __half22float2(h0[p]);
            float2 v1 = __half22float2(h1[p]);
            float2 v2 = __half22float2(h2[p]);
            float2 v3 = __half22float2(h3[p]);
            acc[i].x += wa * v0.x + wb * v1.x + wc * v2.x + wd * v3.x;
            acc[i].y += wa * v0.y + wb * v1.y + wc * v2.y + wd * v3.y;
        }
    }
    for (; j < r1; j++) {
        int s0 = g_col[j];
        float w0 = 0.f;
        if (lane < H) {
            w0 = __expf(leaky(__ldg(as_ + (long)s0 * H + lane) + adv));
            denom += w0;
        }
        const __half2* h0 = (const __half2*)(h + (long)s0 * D);
        #pragma unroll
        for (int i = 0; i < PER2; i++) {
            int k2 = 2 * lane + 64 * i;
            int p  = lane + 32 * i;
            float wa = __shfl_sync(FULL, w0, k2 / C);
            float2 v0 = __half22float2(h0[p]);
            acc[i].x += wa * v0.x;
            acc[i].y += wa * v0.y;
        }
    }

    float rden = __frcp_rn(denom);
    #pragma unroll
    for (int i = 0; i < PER2; i++) {
        int k2 = 2 * lane + 64 * i;
        float rk = __shfl_sync(FULL, rden, k2 / C);
        float2 bv = *(const float2*)&bias[k2];
        float vx = acc[i].x * rk + bv.x;
        float vy = acc[i].y * rk + bv.y;
        vx = vx > 0.f ? vx : __expf(vx) - 1.f;
        vy = vy > 0.f ? vy : __expf(vy) - 1.f;
        *(float2*)&out[(long)node * D + k2] = make_float2(vx, vy);
    }
}

// ---------------- pair scoring head ----------------
__global__ void k_pair(const float* __restrict__ x, const int* __restrict__ n1,
                       const int* __restrict__ n2, const float* __restrict__ linW,
                       const float* __restrict__ linb, float* __restrict__ y) {
    int warp = (blockIdx.x * blockDim.x + threadIdx.x) >> 5;
    int lane = threadIdx.x & 31;
    if (warp >= PAIRS) return;
    int a = n1[warp], b = n2[warp];
    float p0 = 0.f, p1 = 0.f;
    #pragma unroll
    for (int i = 0; i < 4; i++) {
        int k = lane + 32 * i;
        float xv = (k < D2) ? x[(long)a * D2 + k] : x[(long)b * D2 + (k - D2)];
        p0 += xv * linW[k * 2 + 0];
        p1 += xv * linW[k * 2 + 1];
    }
    #pragma unroll
    for (int off = 16; off; off >>= 1) {
        p0 += __shfl_xor_sync(FULL, p0, off);
        p1 += __shfl_xor_sync(FULL, p1, off);
    }
    if (lane == 0) {
        float z0 = p0 + linb[0], z1 = p1 + linb[1];
        y[warp * 2 + 0] = 1.f / (1.f + __expf(-z0));
        y[warp * 2 + 1] = 1.f / (1.f + __expf(-z1));
    }
}

// ---------------- launcher ----------------
extern "C" void kernel_launch(void* const* d_in, const int* in_sizes, int n_in,
                              void* d_out, int out_size) {
    const float* features = (const float*)d_in[0];
    const int*   edge_index = (const int*)d_in[1];
    const int*   n1 = (const int*)d_in[2];
    const int*   n2 = (const int*)d_in[3];
    const float* W1 = (const float*)d_in[4];
    const float* attS1 = (const float*)d_in[5];
    const float* attD1 = (const float*)d_in[6];
    const float* b1 = (const float*)d_in[7];
    const float* W2 = (const float*)d_in[8];
    const float* attS2 = (const float*)d_in[9];
    const float* attD2 = (const float*)d_in[10];
    const float* b2 = (const float*)d_in[11];
    const float* linW = (const float*)d_in[12];
    const float* linb = (const float*)d_in[13];

    float* out  = (float*)d_out;
    float* y    = out;
    float* xout = out + PAIRS * 2;

    int E = in_sizes[1] / 2;

    __half *p_h1, *p_x1h, *p_h2;
    float *p_as1, *p_ad1, *p_as2, *p_ad2;
    uint32_t *p_fAb, *p_fAs, *p_w1b, *p_w1s, *p_w2b, *p_w2s;
    int *p_deg, *p_cursor;
    cudaGetSymbolAddress((void**)&p_h1, g_h1);
    cudaGetSymbolAddress((void**)&p_x1h, g_x1h);
    cudaGetSymbolAddress((void**)&p_h2, g_h2);
    cudaGetSymbolAddress((void**)&p_as1, g_as1);
    cudaGetSymbolAddress((void**)&p_ad1, g_ad1);
    cudaGetSymbolAddress((void**)&p_as2, g_as2);
    cudaGetSymbolAddress((void**)&p_ad2, g_ad2);
    cudaGetSymbolAddress((void**)&p_fAb, g_fAb);
    cudaGetSymbolAddress((void**)&p_fAs, g_fAs);
    cudaGetSymbolAddress((void**)&p_w1b, g_w1b);
    cudaGetSymbolAddress((void**)&p_w1s, g_w1s);
    cudaGetSymbolAddress((void**)&p_w2b, g_w2b);
    cudaGetSymbolAddress((void**)&p_w2s, g_w2s);
    cudaGetSymbolAddress((void**)&p_deg, g_deg);
    cudaGetSymbolAddress((void**)&p_cursor, g_cursor);

    static cudaStream_t s2 = nullptr;
    static cudaEvent_t evFork = nullptr, evJoin = nullptr, evA = nullptr, evG = nullptr;
    if (!s2) {
        cudaStreamCreateWithFlags(&s2, cudaStreamNonBlocking);
        cudaEventCreateWithFlags(&evFork, cudaEventDisableTiming);
        cudaEventCreateWithFlags(&evJoin, cudaEventDisableTiming);
        cudaEventCreateWithFlags(&evA, cudaEventDisableTiming);
        cudaEventCreateWithFlags(&evG, cudaEventDisableTiming);
    }

    int e4blocks = ((E + 3) / 4 + 255) / 256;

    // fork: CSR build on s2 overlaps splits + GEMM1 on main stream
    cudaEventRecord(evFork, 0);
    cudaStreamWaitEvent(s2, evFork, 0);

    cudaMemsetAsync(p_deg, 0, NN * sizeof(int), s2);
    cudaMemsetAsync(p_cursor, 0, NN * sizeof(int), s2);
    k_count<<<e4blocks, 256, 0, s2>>>(edge_index, E);
    k_scan<<<1, 1024, 0, s2>>>();
    k_scatter<<<e4blocks, 256, 0, s2>>>(edge_index, E);
    cudaEventRecord(evJoin, s2);

    // pre-split operands (once), then GEMM1 with fused attn
    k_split_feat<<<(int)(((long)NN * (AKP1 / 4) + 255) / 256), 256>>>(features);
    k_split_w1<<<(AKP1 * D1 + 255) / 256, 256>>>(W1);
    k_split_w2<<<(KP2 * D2 + 255) / 256, 256>>>(W2);
    {
        dim3 grid(D1 / 64, (NN + 127) / 128);
        k_gemm_hs<128, 64><<<grid, 256>>>(p_fAb, p_fAs, p_w1b, p_w1s, p_h1,
                                          NN, AKP1, D1,
                                          attS1, attD1, p_as1, p_ad1);
    }

    cudaStreamWaitEvent(0, evJoin, 0);

    // agg1 lo half, then pipeline: GEMM2-lo on s2 overlaps agg1 hi half
    k_agg1<<<(NHALF * 32 + 255) / 256, 256>>>(p_h1, p_as1, p_ad1, b1, p_x1h, 0, NHALF);
    cudaEventRecord(evA, 0);
    cudaStreamWaitEvent(s2, evA, 0);
    {
        dim3 grid(D2 / 64, NHALF / 128);
        k_gemm_h16<128, 64, 16><<<grid, 256, 0, s2>>>(p_x1h, p_w2b, p_w2s, p_h2,
                                                      NHALF, D1, D2,
                                                      attS2, attD2, p_as2, p_ad2);
    }
    cudaEventRecord(evG, s2);

    k_agg1<<<((NN - NHALF) * 32 + 255) / 256, 256>>>(p_h1, p_as1, p_ad1, b1, p_x1h, NHALF, NN - NHALF);
    {
        dim3 grid(D2 / 64, (NN - NHALF + 127) / 128);
        k_gemm_h16<128, 64, 16><<<grid, 256>>>(p_x1h + (long)NHALF * D1, p_w2b, p_w2s,
                                               p_h2 + (long)NHALF * D2, NN - NHALF, D1, D2,
                                               attS2, attD2,
                                               p_as2 + (long)NHALF * H2, p_ad2 + (long)NHALF * H2);
    }
    cudaStreamWaitEvent(0, evG, 0);

    k_agg<H2, C2><<<(NN * 32 + 255) / 256, 256>>>(p_h2, p_as2, p_ad2, b2, xout, 0, NN);

    // Pair head
    k_pair<<<(PAIRS * 32 + 255) / 256, 256>>>(xout, n1, n2, linW, linb, y);
}